// round 13
// baseline (speedup 1.0000x reference)
#include <cuda_runtime.h>
#include <cuda_fp16.h>
#include <cstdint>

#define T_SEQ 2048
#define BATCH 2
#define EMBED 512
#define NHEADS 8
#define HD 64
#define FFN_DIM 2048
#define NROWS (T_SEQ * BATCH)      // 4096
#define BH (BATCH * NHEADS)        // 16
#define QKV_LD (3 * EMBED)         // 1536
#define ROWSTRIDE (BATCH * QKV_LD) // 3072
#define S32 40
#define SQ 72                      // stride (elems) for 64-col fp16 tiles

// weight-plane segment offsets (elems) -- hi plane only
#define S_SQKV 0
#define S_SWO  3145728
#define S_CQKV 4194304
#define S_CWO  7340032
#define S_FC1  8388608
#define S_FC2  12582912
#define W_TOT  16777216

// fused-attn smem: Q-hi [0,18432); 2 stages of (K-hi + V-hi) (36864 each)
#define FA_QB 18432
#define FA_VOFF 18432
#define FA_SSTG 36864
#define FA_SMEM (FA_QB + 2 * FA_SSTG)  // 92160

// ---------------- device scratch ----------------
__device__ __align__(16) float g_x[NROWS * EMBED];
__device__ __align__(16) float g_y[NROWS * EMBED];
__device__ __align__(16) __half g_xh[NROWS * EMBED], g_xl[NROWS * EMBED];
__device__ __align__(16) __half g_ench[NROWS * EMBED], g_encl[NROWS * EMBED];
__device__ __align__(16) __half g_qkvh[NROWS * QKV_LD], g_qkvl[NROWS * QKV_LD];
__device__ __align__(16) __half g_hidh[NROWS * FFN_DIM], g_hidl[NROWS * FFN_DIM];
__device__ __align__(16) __half g_ah[NROWS * EMBED], g_al[NROWS * EMBED];
__device__ __align__(16) __half g_wbh[W_TOT];
__device__ float g_vsum[BATCH * EMBED];
__device__ float g_vs2[BATCH * EMBED];
__device__ unsigned g_minmax[2];

__device__ __forceinline__ unsigned fenc(float f) {
    unsigned u = __float_as_uint(f);
    return (u & 0x80000000u) ? ~u : (u | 0x80000000u);
}
__device__ __forceinline__ float fdec(unsigned e) {
    return __uint_as_float((e & 0x80000000u) ? (e ^ 0x80000000u) : ~e);
}
__device__ __forceinline__ uint32_t smem_u32(const void* p) {
    uint32_t a;
    asm("{ .reg .u64 t; cvta.to.shared.u64 t, %1; cvt.u32.u64 %0, t; }" : "=r"(a) : "l"(p));
    return a;
}
__device__ __forceinline__ void cpa16(uint32_t d, const void* s) {
    asm volatile("cp.async.cg.shared.global [%0], [%1], 16;" :: "r"(d), "l"(s));
}
#define CPA_COMMIT() asm volatile("cp.async.commit_group;" ::: "memory")
#define CPA_WAIT0()  asm volatile("cp.async.wait_group 0;" ::: "memory")
#define CPA_WAIT1()  asm volatile("cp.async.wait_group 1;" ::: "memory")

__device__ __forceinline__ void ldmx4(uint32_t* r, uint32_t addr) {
    asm volatile("ldmatrix.sync.aligned.m8n8.x4.shared.b16 {%0,%1,%2,%3}, [%4];"
        : "=r"(r[0]), "=r"(r[1]), "=r"(r[2]), "=r"(r[3]) : "r"(addr));
}
__device__ __forceinline__ void ldmx4t(uint32_t* r, uint32_t addr) {
    asm volatile("ldmatrix.sync.aligned.m8n8.x4.trans.shared.b16 {%0,%1,%2,%3}, [%4];"
        : "=r"(r[0]), "=r"(r[1]), "=r"(r[2]), "=r"(r[3]) : "r"(addr));
}
__device__ __forceinline__ void mma16816(float* c, const uint32_t* a, const uint32_t* b) {
    asm volatile("mma.sync.aligned.m16n8k16.row.col.f32.f16.f16.f32 "
        "{%0,%1,%2,%3}, {%4,%5,%6,%7}, {%8,%9}, {%0,%1,%2,%3};"
        : "+f"(c[0]), "+f"(c[1]), "+f"(c[2]), "+f"(c[3])
        : "r"(a[0]), "r"(a[1]), "r"(a[2]), "r"(a[3]), "r"(b[0]), "r"(b[1]));
}
__device__ __forceinline__ void cvt4(float4 v, uint2& uh, uint2& ul) {
    __half2 h01 = __floats2half2_rn(v.x, v.y);
    __half2 h23 = __floats2half2_rn(v.z, v.w);
    float2 f01 = __half22float2(h01);
    float2 f23 = __half22float2(h23);
    __half2 l01 = __floats2half2_rn(v.x - f01.x, v.y - f01.y);
    __half2 l23 = __floats2half2_rn(v.z - f23.x, v.w - f23.y);
    uh.x = *(uint32_t*)&h01; uh.y = *(uint32_t*)&h23;
    ul.x = *(uint32_t*)&l01; ul.y = *(uint32_t*)&l23;
}
__device__ __forceinline__ void cvt2(float v0, float v1, uint32_t& h, uint32_t& l) {
    __half2 hh = __floats2half2_rn(v0, v1);
    float2 hf = __half22float2(hh);
    __half2 ll = __floats2half2_rn(v0 - hf.x, v1 - hf.y);
    h = *(uint32_t*)&hh; l = *(uint32_t*)&ll;
}
__device__ __forceinline__ uint32_t pack2h(float v0, float v1) {
    __half2 hh = __floats2half2_rn(v0, v1);
    return *(uint32_t*)&hh;
}

// ---------------- small kernels ----------------
__global__ void cvt_planes(const float* __restrict__ src,
                           __half* __restrict__ dh,
                           __half* __restrict__ dl, int n4) {
    int i = blockIdx.x * 256 + threadIdx.x;
    if (i >= n4) return;
    float4 v = ((const float4*)src)[i];
    uint2 uh, ul;
    cvt4(v, uh, ul);
    ((uint2*)dh)[i] = uh;
    ((uint2*)dl)[i] = ul;
}

__global__ void cvt_hi(const float* __restrict__ src, __half* __restrict__ dh, int n4) {
    int i = blockIdx.x * 256 + threadIdx.x;
    if (i >= n4) return;
    float4 v = ((const float4*)src)[i];
    __half2 h01 = __floats2half2_rn(v.x, v.y);
    __half2 h23 = __floats2half2_rn(v.z, v.w);
    uint2 uh;
    uh.x = *(uint32_t*)&h01; uh.y = *(uint32_t*)&h23;
    ((uint2*)dh)[i] = uh;
}

__global__ void posembed_kernel(const float* __restrict__ x,
                                const int* __restrict__ tokens) {
    int i = blockIdx.x * 256 + threadIdx.x;
    int c4 = (i & 127) * 4;
    int row = i >> 7;
    int t = row >> 1, b = row & 1;
    int tok = tokens[b * T_SEQ + t];
    float4 v = ((const float4*)x)[i];
    if (tok != 0) {
        float p = (float)(t + 1);
        float* pv = (float*)&v;
#pragma unroll
        for (int e = 0; e < 4; e++) {
            int c = c4 + e;
            int ii = (c < 256) ? c : c - 256;
            float ang = p * expf((float)ii * (-9.210340371976184f / 255.0f));
            pv[e] += (c < 256) ? sinf(ang) : cosf(ang);
        }
    }
    ((float4*)g_x)[i] = v;
    uint2 uh, ul;
    cvt4(v, uh, ul);
    ((uint2*)g_xh)[i] = uh;
    ((uint2*)g_xl)[i] = ul;
}

// vsum (exact: hi+lo) + folded min/max init
__global__ void vsum_kernel(int selfmask) {
    const int bh = blockIdx.x;
    if (bh == 0 && threadIdx.x == 0) {
        if (selfmask) { g_minmax[0] = fenc(0.f); g_minmax[1] = fenc(0.f); }
        else          { g_minmax[0] = 0xFFFFFFFFu; g_minmax[1] = 0u; }
    }
    const int b = bh >> 3, h = bh & 7;
    const __half* vh = g_qkvh + b * QKV_LD + 2 * EMBED + h * HD;
    const __half* vl = g_qkvl + b * QKV_LD + 2 * EMBED + h * HD;
    const int d = threadIdx.x & 63;
    const int part = threadIdx.x >> 6;
    float s = 0.f;
    for (int i = part * 512; i < part * 512 + 512; i++) {
        size_t off = (size_t)i * ROWSTRIDE + d;
        s += __half2float(vh[off]) + __half2float(vl[off]);
    }
    __shared__ float sm[256];
    sm[threadIdx.x] = s;
    __syncthreads();
    if (threadIdx.x < 64)
        g_vsum[b * EMBED + h * HD + d] = sm[d] + sm[64 + d] + sm[128 + d] + sm[192 + d];
}

// vs2[b][n] = sum_c vsum[b][c] * Wo[n][c]
__global__ void vs2_kernel(const float* __restrict__ Wo) {
    int idx = blockIdx.x * 256 + threadIdx.x;  // 1024
    int b = idx >> 9, n = idx & 511;
    const float* vs = g_vsum + b * EMBED;
    const float* w = Wo + (size_t)n * EMBED;
    float s = 0.f;
    for (int c = 0; c < EMBED; c += 4) {
        float4 wv = *(const float4*)(w + c);
        s += vs[c] * wv.x + vs[c + 1] * wv.y + vs[c + 2] * wv.z + vs[c + 3] * wv.w;
    }
    g_vs2[idx] = s;
}

// warp-per-row LN
__global__ __launch_bounds__(256)
void ln_kernel(const float* __restrict__ res, const float* __restrict__ y,
               const float* __restrict__ gam, const float* __restrict__ bet,
               float* __restrict__ out,
               __half* __restrict__ outh, __half* __restrict__ outl) {
    const int row = blockIdx.x * 8 + (threadIdx.x >> 5);
    const int lane = threadIdx.x & 31;
    const size_t base = (size_t)row * EMBED;
    float v[16];
    float s = 0.f, q = 0.f;
#pragma unroll
    for (int k = 0; k < 4; k++) {
        const int c = lane * 4 + k * 128;
        float4 a = *(const float4*)(res + base + c);
        float4 bb = *(const float4*)(y + base + c);
        float t0 = a.x + bb.x, t1 = a.y + bb.y, t2 = a.z + bb.z, t3 = a.w + bb.w;
        v[k * 4 + 0] = t0; v[k * 4 + 1] = t1; v[k * 4 + 2] = t2; v[k * 4 + 3] = t3;
        s += t0 + t1 + t2 + t3;
        q += t0 * t0 + t1 * t1 + t2 * t2 + t3 * t3;
    }
#pragma unroll
    for (int off = 16; off > 0; off >>= 1) {
        s += __shfl_xor_sync(0xffffffffu, s, off);
        q += __shfl_xor_sync(0xffffffffu, q, off);
    }
    const float mu = s * (1.f / 512.f);
    const float var = q * (1.f / 512.f) - mu * mu;
    const float rs = rsqrtf(fmaxf(var, 0.f) + 1e-20f);
#pragma unroll
    for (int k = 0; k < 4; k++) {
        const int c = lane * 4 + k * 128;
        float4 g4 = *(const float4*)(gam + c);
        float4 b4 = *(const float4*)(bet + c);
        float4 o;
        o.x = (v[k * 4 + 0] - mu) * rs * g4.x + b4.x;
        o.y = (v[k * 4 + 1] - mu) * rs * g4.y + b4.y;
        o.z = (v[k * 4 + 2] - mu) * rs * g4.z + b4.z;
        o.w = (v[k * 4 + 3] - mu) * rs * g4.w + b4.w;
        *(float4*)(out + base + c) = o;
        uint2 uh, ul;
        cvt4(o, uh, ul);
        *(uint2*)(outh + base + c) = uh;
        *(uint2*)(outl + base + c) = ul;
    }
}

// ---------------- fused attention: R8 structure, single-plane fp16 (Q,K,S,V hi) ----
__global__ __launch_bounds__(256, 1)
void fused_attn(int selfmask) {
    const int bid = blockIdx.x;
    const int bh = bid & 15, b = bh >> 3, h = bh & 7;
    const int tile = bid >> 4;
    const int bt = (selfmask ? (15 - tile) : tile) * 128;
    extern __shared__ char dyn[];
    const uint32_t u0 = smem_u32(dyn);
    const int tid = threadIdx.x, wid = tid >> 5, lane = tid & 31;
    const int trow = wid * 16;
    const __half* qh = g_qkvh + b * QKV_LD + h * HD;
    const __half* kh = g_qkvh + b * QKV_LD + EMBED + h * HD;
    const __half* vh = g_qkvh + b * QKV_LD + 2 * EMBED + h * HD;
    const int nst = selfmask ? (bt / 128 + 1) : 16;

    // prologue: Q-hi + stage-0 K-hi/V-hi (one group)
#pragma unroll 1
    for (int i = tid; i < 1024; i += 256) {
        int r = i >> 3, c = (i & 7) * 8;
        cpa16(u0 + (r * SQ + c) * 2, qh + (size_t)(bt + r) * ROWSTRIDE + c);
        uint32_t dk = u0 + FA_QB + (r * SQ + c) * 2;
        cpa16(dk,           kh + (size_t)r * ROWSTRIDE + c);
        cpa16(dk + FA_VOFF, vh + (size_t)r * ROWSTRIDE + c);
    }
    CPA_COMMIT();

    uint32_t qfh[4][4];
    float oacc[8][4] = {};
    float lmin = 3.4e38f, lmax = -3.4e38f;

    for (int st = 0; st < nst; st++) {
        const uint32_t sb = u0 + FA_QB + (st & 1) * FA_SSTG;
        if (st + 1 < nst) {
            const uint32_t nb = u0 + FA_QB + ((st + 1) & 1) * FA_SSTG;
            const int s0 = (st + 1) * 128;
#pragma unroll 1
            for (int i = tid; i < 1024; i += 256) {
                int r = i >> 3, c = (i & 7) * 8;
                uint32_t dk = nb + (r * SQ + c) * 2;
                cpa16(dk,           kh + (size_t)(s0 + r) * ROWSTRIDE + c);
                cpa16(dk + FA_VOFF, vh + (size_t)(s0 + r) * ROWSTRIDE + c);
            }
            CPA_COMMIT();
            CPA_WAIT1();
        } else {
            CPA_WAIT0();
        }
        __syncthreads();
        if (st == 0) {
#pragma unroll
            for (int ks = 0; ks < 4; ks++) {
                uint32_t off = u0 + ((trow + (lane & 15)) * SQ + ks * 16 + (lane >> 4) * 8) * 2;
                ldmx4(qfh[ks], off);
            }
        }
        // ---- S = Q @ K^T (full 128 cols, 16 independent accumulators) ----
        float sacc[16][4] = {};
#pragma unroll
        for (int ks = 0; ks < 4; ks++) {
#pragma unroll
            for (int j4 = 0; j4 < 8; j4++) {
                uint32_t off = sb + ((j4 * 16 + ((lane >> 4) & 1) * 8 + (lane & 7)) * SQ
                               + ks * 16 + ((lane >> 3) & 1) * 8) * 2;
                uint32_t kbh[4];
                ldmx4(kbh, off);
#pragma unroll
                for (int jj = 0; jj < 2; jj++)
                    mma16816(sacc[j4 * 2 + jj], qfh[ks], &kbh[jj * 2]);
            }
        }
        // ---- scale/mask/minmax + register repack C-frag -> A-frag (hi only) ----
        const int diag = selfmask && (st == nst - 1);
        const int tg0 = bt + trow + (lane >> 2);
        const int sg0 = st * 128 + (lane & 3) * 2;
        uint32_t sfh[8][4];
#pragma unroll
        for (int j = 0; j < 16; j++) {
            float v0 = sacc[j][0] * 0.125f, v1 = sacc[j][1] * 0.125f;
            float v2 = sacc[j][2] * 0.125f, v3 = sacc[j][3] * 0.125f;
            if (diag) {
                int s = sg0 + j * 8;
                if (s + 0 > tg0) v0 = 0.f;
                if (s + 1 > tg0) v1 = 0.f;
                if (s + 0 > tg0 + 8) v2 = 0.f;
                if (s + 1 > tg0 + 8) v3 = 0.f;
            }
            lmin = fminf(lmin, fminf(fminf(v0, v1), fminf(v2, v3)));
            lmax = fmaxf(lmax, fmaxf(fmaxf(v0, v1), fmaxf(v2, v3)));
            int p = j >> 1, q = (j & 1) * 2;
            sfh[p][q] = pack2h(v0, v1);
            sfh[p][q + 1] = pack2h(v2, v3);
        }
        // ---- O += S @ V (B-frag via ldmatrix.trans on V[s][d]) ----
        const uint32_t vb = sb + FA_VOFF;
#pragma unroll
        for (int p = 0; p < 8; p++) {
#pragma unroll
            for (int jd4 = 0; jd4 < 4; jd4++) {
                uint32_t off = vb + ((p * 16 + (lane & 15)) * SQ + jd4 * 16 + (lane >> 4) * 8) * 2;
                uint32_t vbh[4];
                ldmx4t(vbh, off);
#pragma unroll
                for (int jj = 0; jj < 2; jj++)
                    mma16816(oacc[jd4 * 2 + jj], sfh[p], &vbh[jj * 2]);
            }
        }
        __syncthreads();
    }

    // ---- epilogue: write O_raw fp16 planes ----
    const int r = lane >> 2, tig = lane & 3;
#pragma unroll
    for (int jd = 0; jd < 8; jd++) {
        const int d = jd * 8 + tig * 2;
#pragma unroll
        for (int half = 0; half < 2; half++) {
            const int t = bt + trow + r + half * 8;
            uint32_t hw, lw;
            cvt2(oacc[jd][half * 2], oacc[jd][half * 2 + 1], hw, lw);
            size_t off = (size_t)(t * BATCH + b) * EMBED + h * HD + d;
            *(uint32_t*)(g_ah + off) = hw;
            *(uint32_t*)(g_al + off) = lw;
        }
    }
    // ---- global min/max ----
#pragma unroll
    for (int off = 16; off > 0; off >>= 1) {
        lmin = fminf(lmin, __shfl_xor_sync(0xffffffffu, lmin, off));
        lmax = fmaxf(lmax, __shfl_xor_sync(0xffffffffu, lmax, off));
    }
    __shared__ float rmn[8], rmx[8];
    if (lane == 0) { rmn[wid] = lmin; rmx[wid] = lmax; }
    __syncthreads();
    if (tid == 0) {
        float mn = rmn[0], mx = rmx[0];
#pragma unroll
        for (int w = 1; w < 8; w++) { mn = fminf(mn, rmn[w]); mx = fmaxf(mx, rmx[w]); }
        atomicMin(&g_minmax[0], fenc(mn));
        atomicMax(&g_minmax[1], fenc(mx));
    }
}

// ---------------- mma linear (R8 2-stage pipeline; A hi/lo, B hi) ----------------
// mode 0: fp32 out; 1: fp16 planes out; 2: planes + relu; 3: fp32 + deferred norm
#define LIN_STG 30720
__global__ __launch_bounds__(256)
void mma_linear(const __half* __restrict__ Aqh, const __half* __restrict__ Aql,
                const __half* __restrict__ Akvh, const __half* __restrict__ Akvl,
                int nsplit,
                const __half* __restrict__ Bh,
                const float* __restrict__ bias, int N, int K, int mode,
                const float* __restrict__ vs2,
                float* __restrict__ Cf, __half* __restrict__ Ch,
                __half* __restrict__ Cl) {
    extern __shared__ char dyn[];
    const uint32_t u0 = smem_u32(dyn);
    const int tid = threadIdx.x, wid = tid >> 5, lane = tid & 31;
    const int bn = blockIdx.x * 128, bm = blockIdx.y * 128;
    const __half* Ah = (bn < nsplit) ? Aqh : Akvh;
    const __half* Al = (bn < nsplit) ? Aql : Akvl;
    const int wm = (wid >> 2) * 64, wn = (wid & 3) * 32;

    float acc[4][4][4] = {};
    const int nkt = K >> 5;

#pragma unroll 1
    for (int i = tid; i < 512; i += 256) {
        int r = i >> 2, c = (i & 3) * 8;
        uint32_t d = u0 + (r * S32 + c) * 2;
        cpa16(d,         Ah + (size_t)(bm + r) * K + c);
        cpa16(d + 10240, Al + (size_t)(bm + r) * K + c);
        cpa16(d + 20480, Bh + (size_t)(bn + r) * K + c);
    }
    CPA_COMMIT();

    for (int kt = 0; kt < nkt; kt++) {
        const uint32_t sb = u0 + (kt & 1) * LIN_STG;
        if (kt + 1 < nkt) {
            const uint32_t nb = u0 + ((kt + 1) & 1) * LIN_STG;
            const int kc = (kt + 1) * 32;
#pragma unroll 1
            for (int i = tid; i < 512; i += 256) {
                int r = i >> 2, c = (i & 3) * 8;
                uint32_t d = nb + (r * S32 + c) * 2;
                cpa16(d,         Ah + (size_t)(bm + r) * K + kc + c);
                cpa16(d + 10240, Al + (size_t)(bm + r) * K + kc + c);
                cpa16(d + 20480, Bh + (size_t)(bn + r) * K + kc + c);
            }
            CPA_COMMIT();
            CPA_WAIT1();
        } else {
            CPA_WAIT0();
        }
        __syncthreads();
#pragma unroll
        for (int ks = 0; ks < 2; ks++) {
            uint32_t ah[4][4], al[4][4], bh[2][4];
#pragma unroll
            for (int i = 0; i < 4; i++) {
                uint32_t off = sb + ((wm + i * 16 + (lane & 15)) * S32 + ks * 16 + (lane >> 4) * 8) * 2;
                ldmx4(ah[i], off);
                ldmx4(al[i], off + 10240);
            }
#pragma unroll
            for (int j2 = 0; j2 < 2; j2++) {
                uint32_t off = sb + ((wn + j2 * 16 + ((lane >> 4) & 1) * 8 + (lane & 7)) * S32
                               + ks * 16 + ((lane >> 3) & 1) * 8) * 2;
                ldmx4(bh[j2], off + 20480);
            }
#pragma unroll
            for (int i = 0; i < 4; i++)
#pragma unroll
                for (int j = 0; j < 4; j++) {
                    const uint32_t* bhf = &bh[j >> 1][(j & 1) * 2];
                    mma16816(acc[i][j], ah[i], bhf);
                    mma16816(acc[i][j], al[i], bhf);
                }
        }
        __syncthreads();
    }
    float mn = 0.f, inv = 1.f;
    if (mode == 3) {
        mn = fdec(g_minmax[0]);
        inv = 1.f / (fdec(g_minmax[1]) - mn);
    }
#pragma unroll
    for (int i = 0; i < 4; i++) {
        const int m0 = bm + wm + i * 16 + (lane >> 2);
#pragma unroll
        for (int j = 0; j < 4; j++) {
            const int n0 = bn + wn + j * 8 + (lane & 3) * 2;
            float b0 = bias[n0], b1 = bias[n0 + 1];
#pragma unroll
            for (int half = 0; half < 2; half++) {
                const int m = m0 + half * 8;
                float v0 = acc[i][j][half * 2 + 0];
                float v1 = acc[i][j][half * 2 + 1];
                if (mode == 3) {
                    const int bb = m & 1;
                    v0 = (v0 - mn * vs2[bb * EMBED + n0]) * inv + b0;
                    v1 = (v1 - mn * vs2[bb * EMBED + n0 + 1]) * inv + b1;
                    float2 o = make_float2(v0, v1);
                    *(float2*)(Cf + (size_t)m * N + n0) = o;
                } else {
                    v0 += b0; v1 += b1;
                    if (mode == 2) { v0 = fmaxf(v0, 0.f); v1 = fmaxf(v1, 0.f); }
                    if (mode == 0) {
                        float2 o = make_float2(v0, v1);
                        *(float2*)(Cf + (size_t)m * N + n0) = o;
                    } else {
                        uint32_t hh, ll;
                        cvt2(v0, v1, hh, ll);
                        *(uint32_t*)(Ch + (size_t)m * N + n0) = hh;
                        *(uint32_t*)(Cl + (size_t)m * N + n0) = ll;
                    }
                }
            }
        }
    }
}

// ---------------- host orchestration ----------------
extern "C" void kernel_launch(void* const* d_in, const int* in_sizes, int n_in,
                              void* d_out, int out_size) {
    const float* x         = (const float*)d_in[0];
    const float* enc_out   = (const float*)d_in[1];
    const int*   tokens    = (const int*)d_in[2];
    const float* self_Wqkv = (const float*)d_in[3];
    const float* self_bqkv = (const float*)d_in[4];
    const float* self_Wo   = (const float*)d_in[5];
    const float* self_bo   = (const float*)d_in[6];
    const float* cross_Wqkv= (const float*)d_in[7];
    const float* cross_bqkv= (const float*)d_in[8];
    const float* cross_Wo  = (const float*)d_in[9];
    const float* cross_bo  = (const float*)d_in[10];
    const float* fc1_w     = (const float*)d_in[11];
    const float* fc1_b     = (const float*)d_in[12];
    const float* fc2_w     = (const float*)d_in[13];
    const float* fc2_b     = (const float*)d_in[14];
    const float* ln1_g     = (const float*)d_in[15];
    const float* ln1_b     = (const float*)d_in[16];
    const float* ln2_g     = (const float*)d_in[17];
    const float* ln2_b     = (const float*)d_in[18];
    const float* ln3_g     = (const float*)d_in[19];
    const float* ln3_b     = (const float*)d_in[20];

    float *px, *py, *pvs2;
    __half *pxh, *pxl, *pench, *pencl, *pqkvh, *pqkvl, *phidh, *phidl, *pah, *pal, *pwbh;
    cudaGetSymbolAddress((void**)&px, g_x);
    cudaGetSymbolAddress((void**)&py, g_y);
    cudaGetSymbolAddress((void**)&pvs2, g_vs2);
    cudaGetSymbolAddress((void**)&pxh, g_xh);
    cudaGetSymbolAddress((void**)&pxl, g_xl);
    cudaGetSymbolAddress((void**)&pench, g_ench);
    cudaGetSymbolAddress((void**)&pencl, g_encl);
    cudaGetSymbolAddress((void**)&pqkvh, g_qkvh);
    cudaGetSymbolAddress((void**)&pqkvl, g_qkvl);
    cudaGetSymbolAddress((void**)&phidh, g_hidh);
    cudaGetSymbolAddress((void**)&phidl, g_hidl);
    cudaGetSymbolAddress((void**)&pah, g_ah);
    cudaGetSymbolAddress((void**)&pal, g_al);
    cudaGetSymbolAddress((void**)&pwbh, g_wbh);

    const int SM_LIN = 2 * LIN_STG;  // 61440
    cudaFuncSetAttribute(mma_linear, cudaFuncAttributeMaxDynamicSharedMemorySize, SM_LIN);
    cudaFuncSetAttribute(fused_attn, cudaFuncAttributeMaxDynamicSharedMemorySize, FA_SMEM);

    auto cvtw = [&](const float* src, size_t off, int n) {
        cvt_hi<<<(n / 4 + 255) / 256, 256>>>(src, pwbh + off, n / 4);
    };
    cvtw(self_Wqkv, S_SQKV, 4 * QKV_LD * EMBED);
    cvtw(self_Wo,   S_SWO,  4 * EMBED * EMBED);
    cvtw(cross_Wqkv,S_CQKV, 4 * QKV_LD * EMBED);
    cvtw(cross_Wo,  S_CWO,  4 * EMBED * EMBED);
    cvtw(fc1_w,     S_FC1,  4 * FFN_DIM * EMBED);
    cvtw(fc2_w,     S_FC2,  4 * EMBED * FFN_DIM);
    cvt_planes<<<(NROWS * EMBED / 4 + 255) / 256, 256>>>(enc_out, pench, pencl, NROWS * EMBED / 4);

    posembed_kernel<<<NROWS * EMBED / 4 / 256, 256>>>(x, tokens);

    const int BIG = 1 << 30;
    for (int l = 0; l < 4; l++) {
        // ---- self attention ----
        mma_linear<<<dim3(12, 32), 256, SM_LIN>>>(pxh, pxl, pxh, pxl, BIG,
            pwbh + S_SQKV + (size_t)l * QKV_LD * EMBED,
            self_bqkv + l * QKV_LD, QKV_LD, EMBED, 1, nullptr, nullptr, pqkvh, pqkvl);
        vsum_kernel<<<16, 256>>>(1);
        fused_attn<<<256, 256, FA_SMEM>>>(1);
        vs2_kernel<<<4, 256>>>(self_Wo + (size_t)l * EMBED * EMBED);
        mma_linear<<<dim3(4, 32), 256, SM_LIN>>>(pah, pal, pah, pal, BIG,
            pwbh + S_SWO + (size_t)l * EMBED * EMBED,
            self_bo + l * EMBED, EMBED, EMBED, 3, pvs2, py, nullptr, nullptr);
        ln_kernel<<<NROWS / 8, 256>>>(px, py, ln1_g + l * EMBED, ln1_b + l * EMBED, px, pxh, pxl);

        // ---- cross attention ----
        mma_linear<<<dim3(12, 32), 256, SM_LIN>>>(pxh, pxl, pench, pencl, EMBED,
            pwbh + S_CQKV + (size_t)l * QKV_LD * EMBED,
            cross_bqkv + l * QKV_LD, QKV_LD, EMBED, 1, nullptr, nullptr, pqkvh, pqkvl);
        vsum_kernel<<<16, 256>>>(0);
        fused_attn<<<256, 256, FA_SMEM>>>(0);
        vs2_kernel<<<4, 256>>>(cross_Wo + (size_t)l * EMBED * EMBED);
        mma_linear<<<dim3(4, 32), 256, SM_LIN>>>(pah, pal, pah, pal, BIG,
            pwbh + S_CWO + (size_t)l * EMBED * EMBED,
            cross_bo + l * EMBED, EMBED, EMBED, 3, pvs2, py, nullptr, nullptr);
        ln_kernel<<<NROWS / 8, 256>>>(px, py, ln2_g + l * EMBED, ln2_b + l * EMBED, px, pxh, pxl);

        // ---- FFN ----
        mma_linear<<<dim3(16, 32), 256, SM_LIN>>>(pxh, pxl, pxh, pxl, BIG,
            pwbh + S_FC1 + (size_t)l * FFN_DIM * EMBED,
            fc1_b + l * FFN_DIM, FFN_DIM, EMBED, 2, nullptr, nullptr, phidh, phidl);
        mma_linear<<<dim3(4, 32), 256, SM_LIN>>>(phidh, phidl, phidh, phidl, BIG,
            pwbh + S_FC2 + (size_t)l * EMBED * FFN_DIM,
            fc2_b + l * EMBED, EMBED, FFN_DIM, 0, nullptr, py, nullptr, nullptr);
        float* lnout = (l == 3) ? (float*)d_out : px;
        ln_kernel<<<NROWS / 8, 256>>>(px, py, ln3_g + l * EMBED, ln3_b + l * EMBED, lnout, pxh, pxl);
    }
}

// round 14
// speedup vs baseline: 1.7904x; 1.7904x over previous
#include <cuda_runtime.h>
#include <cuda_fp16.h>
#include <cstdint>

#define T_SEQ 2048
#define BATCH 2
#define EMBED 512
#define NHEADS 8
#define HD 64
#define FFN_DIM 2048
#define NROWS (T_SEQ * BATCH)      // 4096
#define BH (BATCH * NHEADS)        // 16
#define QKV_LD (3 * EMBED)         // 1536
#define ROWSTRIDE (BATCH * QKV_LD) // 3072
#define S32 40
#define SQ 72

// weight-plane segment offsets (elems) -- hi plane only
#define S_SQKV 0
#define S_SWO  3145728
#define S_CQKV 4194304
#define S_CWO  7340032
#define S_FC1  8388608
#define S_FC2  12582912
#define W_TOT  16777216

// fused-attn smem: Q-hi [0,18432); 2 stages of (K-hi + V-hi) (36864 each)
#define FA_QB 18432
#define FA_VOFF 18432
#define FA_SSTG 36864
#define FA_SMEM (FA_QB + 2 * FA_SSTG)  // 92160

// ---------------- device scratch (pure fp16 activations + fp32 residual) ----------------
__device__ __align__(16) float g_x[NROWS * EMBED];
__device__ __align__(16) float g_y[NROWS * EMBED];
__device__ __align__(16) __half g_xh[NROWS * EMBED];
__device__ __align__(16) __half g_ench[NROWS * EMBED];
__device__ __align__(16) __half g_qkvh[NROWS * QKV_LD];
__device__ __align__(16) __half g_hidh[NROWS * FFN_DIM];
__device__ __align__(16) __half g_ah[NROWS * EMBED];
__device__ __align__(16) __half g_wbh[W_TOT];
__device__ float g_vsum[BATCH * EMBED];
__device__ float g_vs2[BATCH * EMBED];
__device__ unsigned g_minmax[2];

__device__ __forceinline__ unsigned fenc(float f) {
    unsigned u = __float_as_uint(f);
    return (u & 0x80000000u) ? ~u : (u | 0x80000000u);
}
__device__ __forceinline__ float fdec(unsigned e) {
    return __uint_as_float((e & 0x80000000u) ? (e ^ 0x80000000u) : ~e);
}
__device__ __forceinline__ uint32_t smem_u32(const void* p) {
    uint32_t a;
    asm("{ .reg .u64 t; cvta.to.shared.u64 t, %1; cvt.u32.u64 %0, t; }" : "=r"(a) : "l"(p));
    return a;
}
__device__ __forceinline__ void cpa16(uint32_t d, const void* s) {
    asm volatile("cp.async.cg.shared.global [%0], [%1], 16;" :: "r"(d), "l"(s));
}
#define CPA_COMMIT() asm volatile("cp.async.commit_group;" ::: "memory")
#define CPA_WAIT0()  asm volatile("cp.async.wait_group 0;" ::: "memory")
#define CPA_WAIT1()  asm volatile("cp.async.wait_group 1;" ::: "memory")

__device__ __forceinline__ void ldmx4(uint32_t* r, uint32_t addr) {
    asm volatile("ldmatrix.sync.aligned.m8n8.x4.shared.b16 {%0,%1,%2,%3}, [%4];"
        : "=r"(r[0]), "=r"(r[1]), "=r"(r[2]), "=r"(r[3]) : "r"(addr));
}
__device__ __forceinline__ void ldmx4t(uint32_t* r, uint32_t addr) {
    asm volatile("ldmatrix.sync.aligned.m8n8.x4.trans.shared.b16 {%0,%1,%2,%3}, [%4];"
        : "=r"(r[0]), "=r"(r[1]), "=r"(r[2]), "=r"(r[3]) : "r"(addr));
}
__device__ __forceinline__ void mma16816(float* c, const uint32_t* a, const uint32_t* b) {
    asm volatile("mma.sync.aligned.m16n8k16.row.col.f32.f16.f16.f32 "
        "{%0,%1,%2,%3}, {%4,%5,%6,%7}, {%8,%9}, {%0,%1,%2,%3};"
        : "+f"(c[0]), "+f"(c[1]), "+f"(c[2]), "+f"(c[3])
        : "r"(a[0]), "r"(a[1]), "r"(a[2]), "r"(a[3]), "r"(b[0]), "r"(b[1]));
}
__device__ __forceinline__ uint2 pack4h(float4 v) {
    __half2 h01 = __floats2half2_rn(v.x, v.y);
    __half2 h23 = __floats2half2_rn(v.z, v.w);
    uint2 u;
    u.x = *(uint32_t*)&h01; u.y = *(uint32_t*)&h23;
    return u;
}
__device__ __forceinline__ uint32_t pack2h(float v0, float v1) {
    __half2 hh = __floats2half2_rn(v0, v1);
    return *(uint32_t*)&hh;
}

// ---------------- small kernels ----------------
__global__ void cvt_hi(const float* __restrict__ src, __half* __restrict__ dh, int n4) {
    int i = blockIdx.x * 256 + threadIdx.x;
    if (i >= n4) return;
    ((uint2*)dh)[i] = pack4h(((const float4*)src)[i]);
}

__global__ void posembed_kernel(const float* __restrict__ x,
                                const int* __restrict__ tokens) {
    int i = blockIdx.x * 256 + threadIdx.x;
    int c4 = (i & 127) * 4;
    int row = i >> 7;
    int t = row >> 1, b = row & 1;
    int tok = tokens[b * T_SEQ + t];
    float4 v = ((const float4*)x)[i];
    if (tok != 0) {
        float p = (float)(t + 1);
        float* pv = (float*)&v;
#pragma unroll
        for (int e = 0; e < 4; e++) {
            int c = c4 + e;
            int ii = (c < 256) ? c : c - 256;
            float ang = p * expf((float)ii * (-9.210340371976184f / 255.0f));
            pv[e] += (c < 256) ? sinf(ang) : cosf(ang);
        }
    }
    ((float4*)g_x)[i] = v;
    ((uint2*)g_xh)[i] = pack4h(v);
}

// vsum over V-hi (matches the V actually used by AV) + folded min/max init
__global__ void vsum_kernel(int selfmask) {
    const int bh = blockIdx.x;
    if (bh == 0 && threadIdx.x == 0) {
        if (selfmask) { g_minmax[0] = fenc(0.f); g_minmax[1] = fenc(0.f); }
        else          { g_minmax[0] = 0xFFFFFFFFu; g_minmax[1] = 0u; }
    }
    const int b = bh >> 3, h = bh & 7;
    const __half* vh = g_qkvh + b * QKV_LD + 2 * EMBED + h * HD;
    const int d = threadIdx.x & 63;
    const int part = threadIdx.x >> 6;
    float s = 0.f;
    for (int i = part * 512; i < part * 512 + 512; i++)
        s += __half2float(vh[(size_t)i * ROWSTRIDE + d]);
    __shared__ float sm[256];
    sm[threadIdx.x] = s;
    __syncthreads();
    if (threadIdx.x < 64)
        g_vsum[b * EMBED + h * HD + d] = sm[d] + sm[64 + d] + sm[128 + d] + sm[192 + d];
}

// vs2[b][n] = sum_c vsum[b][c] * Wo_hi[n][c]  (consistent with the fp16 proj GEMM)
__global__ void vs2_kernel(const __half* __restrict__ Wo) {
    int idx = blockIdx.x * 256 + threadIdx.x;  // 1024
    int b = idx >> 9, n = idx & 511;
    const float* vs = g_vsum + b * EMBED;
    const __half2* w2 = (const __half2*)(Wo + (size_t)n * EMBED);
    float s = 0.f;
    for (int c2 = 0; c2 < 256; c2++) {
        float2 f = __half22float2(w2[c2]);
        s += vs[2 * c2] * f.x + vs[2 * c2 + 1] * f.y;
    }
    g_vs2[idx] = s;
}

// warp-per-row LN (fp32 residual out + fp16 hi plane)
__global__ __launch_bounds__(256)
void ln_kernel(const float* __restrict__ res, const float* __restrict__ y,
               const float* __restrict__ gam, const float* __restrict__ bet,
               float* __restrict__ out, __half* __restrict__ outh) {
    const int row = blockIdx.x * 8 + (threadIdx.x >> 5);
    const int lane = threadIdx.x & 31;
    const size_t base = (size_t)row * EMBED;
    float v[16];
    float s = 0.f, q = 0.f;
#pragma unroll
    for (int k = 0; k < 4; k++) {
        const int c = lane * 4 + k * 128;
        float4 a = *(const float4*)(res + base + c);
        float4 bb = *(const float4*)(y + base + c);
        float t0 = a.x + bb.x, t1 = a.y + bb.y, t2 = a.z + bb.z, t3 = a.w + bb.w;
        v[k * 4 + 0] = t0; v[k * 4 + 1] = t1; v[k * 4 + 2] = t2; v[k * 4 + 3] = t3;
        s += t0 + t1 + t2 + t3;
        q += t0 * t0 + t1 * t1 + t2 * t2 + t3 * t3;
    }
#pragma unroll
    for (int off = 16; off > 0; off >>= 1) {
        s += __shfl_xor_sync(0xffffffffu, s, off);
        q += __shfl_xor_sync(0xffffffffu, q, off);
    }
    const float mu = s * (1.f / 512.f);
    const float var = q * (1.f / 512.f) - mu * mu;
    const float rs = rsqrtf(fmaxf(var, 0.f) + 1e-20f);
#pragma unroll
    for (int k = 0; k < 4; k++) {
        const int c = lane * 4 + k * 128;
        float4 g4 = *(const float4*)(gam + c);
        float4 b4 = *(const float4*)(bet + c);
        float4 o;
        o.x = (v[k * 4 + 0] - mu) * rs * g4.x + b4.x;
        o.y = (v[k * 4 + 1] - mu) * rs * g4.y + b4.y;
        o.z = (v[k * 4 + 2] - mu) * rs * g4.z + b4.z;
        o.w = (v[k * 4 + 3] - mu) * rs * g4.w + b4.w;
        *(float4*)(out + base + c) = o;
        *(uint2*)(outh + base + c) = pack4h(o);
    }
}

// ---------------- fused attention: single-plane fp16 (R13-verified numerics) ----------------
__global__ __launch_bounds__(256, 1)
void fused_attn(int selfmask) {
    const int bid = blockIdx.x;
    const int bh = bid & 15, b = bh >> 3, h = bh & 7;
    const int tile = bid >> 4;
    const int bt = (selfmask ? (15 - tile) : tile) * 128;
    extern __shared__ char dyn[];
    const uint32_t u0 = smem_u32(dyn);
    const int tid = threadIdx.x, wid = tid >> 5, lane = tid & 31;
    const int trow = wid * 16;
    const __half* qh = g_qkvh + b * QKV_LD + h * HD;
    const __half* kh = g_qkvh + b * QKV_LD + EMBED + h * HD;
    const __half* vh = g_qkvh + b * QKV_LD + 2 * EMBED + h * HD;
    const int nst = selfmask ? (bt / 128 + 1) : 16;

#pragma unroll 1
    for (int i = tid; i < 1024; i += 256) {
        int r = i >> 3, c = (i & 7) * 8;
        cpa16(u0 + (r * SQ + c) * 2, qh + (size_t)(bt + r) * ROWSTRIDE + c);
        uint32_t dk = u0 + FA_QB + (r * SQ + c) * 2;
        cpa16(dk,           kh + (size_t)r * ROWSTRIDE + c);
        cpa16(dk + FA_VOFF, vh + (size_t)r * ROWSTRIDE + c);
    }
    CPA_COMMIT();

    uint32_t qfh[4][4];
    float oacc[8][4] = {};
    float lmin = 3.4e38f, lmax = -3.4e38f;

    for (int st = 0; st < nst; st++) {
        const uint32_t sb = u0 + FA_QB + (st & 1) * FA_SSTG;
        if (st + 1 < nst) {
            const uint32_t nb = u0 + FA_QB + ((st + 1) & 1) * FA_SSTG;
            const int s0 = (st + 1) * 128;
#pragma unroll 1
            for (int i = tid; i < 1024; i += 256) {
                int r = i >> 3, c = (i & 7) * 8;
                uint32_t dk = nb + (r * SQ + c) * 2;
                cpa16(dk,           kh + (size_t)(s0 + r) * ROWSTRIDE + c);
                cpa16(dk + FA_VOFF, vh + (size_t)(s0 + r) * ROWSTRIDE + c);
            }
            CPA_COMMIT();
            CPA_WAIT1();
        } else {
            CPA_WAIT0();
        }
        __syncthreads();
        if (st == 0) {
#pragma unroll
            for (int ks = 0; ks < 4; ks++) {
                uint32_t off = u0 + ((trow + (lane & 15)) * SQ + ks * 16 + (lane >> 4) * 8) * 2;
                ldmx4(qfh[ks], off);
            }
        }
        // ---- S = Q @ K^T ----
        float sacc[16][4] = {};
#pragma unroll
        for (int ks = 0; ks < 4; ks++) {
#pragma unroll
            for (int j4 = 0; j4 < 8; j4++) {
                uint32_t off = sb + ((j4 * 16 + ((lane >> 4) & 1) * 8 + (lane & 7)) * SQ
                               + ks * 16 + ((lane >> 3) & 1) * 8) * 2;
                uint32_t kbh[4];
                ldmx4(kbh, off);
#pragma unroll
                for (int jj = 0; jj < 2; jj++)
                    mma16816(sacc[j4 * 2 + jj], qfh[ks], &kbh[jj * 2]);
            }
        }
        // ---- scale/mask/minmax + register repack C-frag -> A-frag ----
        const int diag = selfmask && (st == nst - 1);
        const int tg0 = bt + trow + (lane >> 2);
        const int sg0 = st * 128 + (lane & 3) * 2;
        uint32_t sfh[8][4];
#pragma unroll
        for (int j = 0; j < 16; j++) {
            float v0 = sacc[j][0] * 0.125f, v1 = sacc[j][1] * 0.125f;
            float v2 = sacc[j][2] * 0.125f, v3 = sacc[j][3] * 0.125f;
            if (diag) {
                int s = sg0 + j * 8;
                if (s + 0 > tg0) v0 = 0.f;
                if (s + 1 > tg0) v1 = 0.f;
                if (s + 0 > tg0 + 8) v2 = 0.f;
                if (s + 1 > tg0 + 8) v3 = 0.f;
            }
            lmin = fminf(lmin, fminf(fminf(v0, v1), fminf(v2, v3)));
            lmax = fmaxf(lmax, fmaxf(fmaxf(v0, v1), fmaxf(v2, v3)));
            int p = j >> 1, q = (j & 1) * 2;
            sfh[p][q] = pack2h(v0, v1);
            sfh[p][q + 1] = pack2h(v2, v3);
        }
        // ---- O += S @ V ----
        const uint32_t vb = sb + FA_VOFF;
#pragma unroll
        for (int p = 0; p < 8; p++) {
#pragma unroll
            for (int jd4 = 0; jd4 < 4; jd4++) {
                uint32_t off = vb + ((p * 16 + (lane & 15)) * SQ + jd4 * 16 + (lane >> 4) * 8) * 2;
                uint32_t vbh[4];
                ldmx4t(vbh, off);
#pragma unroll
                for (int jj = 0; jj < 2; jj++)
                    mma16816(oacc[jd4 * 2 + jj], sfh[p], &vbh[jj * 2]);
            }
        }
        __syncthreads();
    }

    // ---- epilogue: write O_raw hi plane ----
    const int r = lane >> 2, tig = lane & 3;
#pragma unroll
    for (int jd = 0; jd < 8; jd++) {
        const int d = jd * 8 + tig * 2;
#pragma unroll
        for (int half = 0; half < 2; half++) {
            const int t = bt + trow + r + half * 8;
            size_t off = (size_t)(t * BATCH + b) * EMBED + h * HD + d;
            *(uint32_t*)(g_ah + off) = pack2h(oacc[jd][half * 2], oacc[jd][half * 2 + 1]);
        }
    }
#pragma unroll
    for (int off = 16; off > 0; off >>= 1) {
        lmin = fminf(lmin, __shfl_xor_sync(0xffffffffu, lmin, off));
        lmax = fmaxf(lmax, __shfl_xor_sync(0xffffffffu, lmax, off));
    }
    __shared__ float rmn[8], rmx[8];
    if (lane == 0) { rmn[wid] = lmin; rmx[wid] = lmax; }
    __syncthreads();
    if (tid == 0) {
        float mn = rmn[0], mx = rmx[0];
#pragma unroll
        for (int w = 1; w < 8; w++) { mn = fminf(mn, rmn[w]); mx = fmaxf(mx, rmx[w]); }
        atomicMin(&g_minmax[0], fenc(mn));
        atomicMax(&g_minmax[1], fenc(mx));
    }
}

// ---------------- mma linear: pure fp16 A-hi x B-hi, fp32 accumulate ----------------
// mode 0: fp32 out; 1: fp16 hi out; 2: hi + relu; 3: fp32 + deferred minmax norm
#define LIN_STG 20480
__global__ __launch_bounds__(256)
void mma_linear(const __half* __restrict__ Aqh, const __half* __restrict__ Akvh,
                int nsplit,
                const __half* __restrict__ Bh,
                const float* __restrict__ bias, int N, int K, int mode,
                const float* __restrict__ vs2,
                float* __restrict__ Cf, __half* __restrict__ Ch) {
    extern __shared__ char dyn[];
    const uint32_t u0 = smem_u32(dyn);
    const int tid = threadIdx.x, wid = tid >> 5, lane = tid & 31;
    const int bn = blockIdx.x * 128, bm = blockIdx.y * 128;
    const __half* Ah = (bn < nsplit) ? Aqh : Akvh;
    const int wm = (wid >> 2) * 64, wn = (wid & 3) * 32;

    float acc[4][4][4] = {};
    const int nkt = K >> 5;

#pragma unroll 1
    for (int i = tid; i < 512; i += 256) {
        int r = i >> 2, c = (i & 3) * 8;
        uint32_t d = u0 + (r * S32 + c) * 2;
        cpa16(d,         Ah + (size_t)(bm + r) * K + c);
        cpa16(d + 10240, Bh + (size_t)(bn + r) * K + c);
    }
    CPA_COMMIT();

    for (int kt = 0; kt < nkt; kt++) {
        const uint32_t sb = u0 + (kt & 1) * LIN_STG;
        if (kt + 1 < nkt) {
            const uint32_t nb = u0 + ((kt + 1) & 1) * LIN_STG;
            const int kc = (kt + 1) * 32;
#pragma unroll 1
            for (int i = tid; i < 512; i += 256) {
                int r = i >> 2, c = (i & 3) * 8;
                uint32_t d = nb + (r * S32 + c) * 2;
                cpa16(d,         Ah + (size_t)(bm + r) * K + kc + c);
                cpa16(d + 10240, Bh + (size_t)(bn + r) * K + kc + c);
            }
            CPA_COMMIT();
            CPA_WAIT1();
        } else {
            CPA_WAIT0();
        }
        __syncthreads();
#pragma unroll
        for (int ks = 0; ks < 2; ks++) {
            uint32_t ah[4][4], bh[2][4];
#pragma unroll
            for (int i = 0; i < 4; i++) {
                uint32_t off = sb + ((wm + i * 16 + (lane & 15)) * S32 + ks * 16 + (lane >> 4) * 8) * 2;
                ldmx4(ah[i], off);
            }
#pragma unroll
            for (int j2 = 0; j2 < 2; j2++) {
                uint32_t off = sb + ((wn + j2 * 16 + ((lane >> 4) & 1) * 8 + (lane & 7)) * S32
                               + ks * 16 + ((lane >> 3) & 1) * 8) * 2;
                ldmx4(bh[j2], off + 10240);
            }
#pragma unroll
            for (int i = 0; i < 4; i++)
#pragma unroll
                for (int j = 0; j < 4; j++)
                    mma16816(acc[i][j], ah[i], &bh[j >> 1][(j & 1) * 2]);
        }
        __syncthreads();
    }
    float mn = 0.f, inv = 1.f;
    if (mode == 3) {
        mn = fdec(g_minmax[0]);
        inv = 1.f / (fdec(g_minmax[1]) - mn);
    }
#pragma unroll
    for (int i = 0; i < 4; i++) {
        const int m0 = bm + wm + i * 16 + (lane >> 2);
#pragma unroll
        for (int j = 0; j < 4; j++) {
            const int n0 = bn + wn + j * 8 + (lane & 3) * 2;
            float b0 = bias[n0], b1 = bias[n0 + 1];
#pragma unroll
            for (int half = 0; half < 2; half++) {
                const int m = m0 + half * 8;
                float v0 = acc[i][j][half * 2 + 0];
                float v1 = acc[i][j][half * 2 + 1];
                if (mode == 3) {
                    const int bb = m & 1;
                    v0 = (v0 - mn * vs2[bb * EMBED + n0]) * inv + b0;
                    v1 = (v1 - mn * vs2[bb * EMBED + n0 + 1]) * inv + b1;
                    *(float2*)(Cf + (size_t)m * N + n0) = make_float2(v0, v1);
                } else {
                    v0 += b0; v1 += b1;
                    if (mode == 2) { v0 = fmaxf(v0, 0.f); v1 = fmaxf(v1, 0.f); }
                    if (mode == 0) {
                        *(float2*)(Cf + (size_t)m * N + n0) = make_float2(v0, v1);
                    } else {
                        *(uint32_t*)(Ch + (size_t)m * N + n0) = pack2h(v0, v1);
                    }
                }
            }
        }
    }
}

// ---------------- host orchestration ----------------
extern "C" void kernel_launch(void* const* d_in, const int* in_sizes, int n_in,
                              void* d_out, int out_size) {
    const float* x         = (const float*)d_in[0];
    const float* enc_out   = (const float*)d_in[1];
    const int*   tokens    = (const int*)d_in[2];
    const float* self_Wqkv = (const float*)d_in[3];
    const float* self_bqkv = (const float*)d_in[4];
    const float* self_Wo   = (const float*)d_in[5];
    const float* self_bo   = (const float*)d_in[6];
    const float* cross_Wqkv= (const float*)d_in[7];
    const float* cross_bqkv= (const float*)d_in[8];
    const float* cross_Wo  = (const float*)d_in[9];
    const float* cross_bo  = (const float*)d_in[10];
    const float* fc1_w     = (const float*)d_in[11];
    const float* fc1_b     = (const float*)d_in[12];
    const float* fc2_w     = (const float*)d_in[13];
    const float* fc2_b     = (const float*)d_in[14];
    const float* ln1_g     = (const float*)d_in[15];
    const float* ln1_b     = (const float*)d_in[16];
    const float* ln2_g     = (const float*)d_in[17];
    const float* ln2_b     = (const float*)d_in[18];
    const float* ln3_g     = (const float*)d_in[19];
    const float* ln3_b     = (const float*)d_in[20];

    float *px, *py, *pvs2;
    __half *pxh, *pench, *pqkvh, *phidh, *pah, *pwbh;
    cudaGetSymbolAddress((void**)&px, g_x);
    cudaGetSymbolAddress((void**)&py, g_y);
    cudaGetSymbolAddress((void**)&pvs2, g_vs2);
    cudaGetSymbolAddress((void**)&pxh, g_xh);
    cudaGetSymbolAddress((void**)&pench, g_ench);
    cudaGetSymbolAddress((void**)&pqkvh, g_qkvh);
    cudaGetSymbolAddress((void**)&phidh, g_hidh);
    cudaGetSymbolAddress((void**)&pah, g_ah);
    cudaGetSymbolAddress((void**)&pwbh, g_wbh);

    const int SM_LIN = 2 * LIN_STG;  // 40960
    cudaFuncSetAttribute(mma_linear, cudaFuncAttributeMaxDynamicSharedMemorySize, SM_LIN);
    cudaFuncSetAttribute(fused_attn, cudaFuncAttributeMaxDynamicSharedMemorySize, FA_SMEM);

    auto cvtw = [&](const float* src, size_t off, int n) {
        cvt_hi<<<(n / 4 + 255) / 256, 256>>>(src, pwbh + off, n / 4);
    };
    cvtw(self_Wqkv, S_SQKV, 4 * QKV_LD * EMBED);
    cvtw(self_Wo,   S_SWO,  4 * EMBED * EMBED);
    cvtw(cross_Wqkv,S_CQKV, 4 * QKV_LD * EMBED);
    cvtw(cross_Wo,  S_CWO,  4 * EMBED * EMBED);
    cvtw(fc1_w,     S_FC1,  4 * FFN_DIM * EMBED);
    cvtw(fc2_w,     S_FC2,  4 * EMBED * FFN_DIM);
    cvt_hi<<<(NROWS * EMBED / 4 + 255) / 256, 256>>>(enc_out, pench, NROWS * EMBED / 4);

    posembed_kernel<<<NROWS * EMBED / 4 / 256, 256>>>(x, tokens);

    const int BIG = 1 << 30;
    for (int l = 0; l < 4; l++) {
        // ---- self attention ----
        mma_linear<<<dim3(12, 32), 256, SM_LIN>>>(pxh, pxh, BIG,
            pwbh + S_SQKV + (size_t)l * QKV_LD * EMBED,
            self_bqkv + l * QKV_LD, QKV_LD, EMBED, 1, nullptr, nullptr, pqkvh);
        vsum_kernel<<<16, 256>>>(1);
        fused_attn<<<256, 256, FA_SMEM>>>(1);
        vs2_kernel<<<4, 256>>>(pwbh + S_SWO + (size_t)l * EMBED * EMBED);
        mma_linear<<<dim3(4, 32), 256, SM_LIN>>>(pah, pah, BIG,
            pwbh + S_SWO + (size_t)l * EMBED * EMBED,
            self_bo + l * EMBED, EMBED, EMBED, 3, pvs2, py, nullptr);
        ln_kernel<<<NROWS / 8, 256>>>(px, py, ln1_g + l * EMBED, ln1_b + l * EMBED, px, pxh);

        // ---- cross attention ----
        mma_linear<<<dim3(12, 32), 256, SM_LIN>>>(pxh, pench, EMBED,
            pwbh + S_CQKV + (size_t)l * QKV_LD * EMBED,
            cross_bqkv + l * QKV_LD, QKV_LD, EMBED, 1, nullptr, nullptr, pqkvh);
        vsum_kernel<<<16, 256>>>(0);
        fused_attn<<<256, 256, FA_SMEM>>>(0);
        vs2_kernel<<<4, 256>>>(pwbh + S_CWO + (size_t)l * EMBED * EMBED);
        mma_linear<<<dim3(4, 32), 256, SM_LIN>>>(pah, pah, BIG,
            pwbh + S_CWO + (size_t)l * EMBED * EMBED,
            cross_bo + l * EMBED, EMBED, EMBED, 3, pvs2, py, nullptr);
        ln_kernel<<<NROWS / 8, 256>>>(px, py, ln2_g + l * EMBED, ln2_b + l * EMBED, px, pxh);

        // ---- FFN ----
        mma_linear<<<dim3(16, 32), 256, SM_LIN>>>(pxh, pxh, BIG,
            pwbh + S_FC1 + (size_t)l * FFN_DIM * EMBED,
            fc1_b + l * FFN_DIM, FFN_DIM, EMBED, 2, nullptr, nullptr, phidh);
        mma_linear<<<dim3(4, 32), 256, SM_LIN>>>(phidh, phidh, BIG,
            pwbh + S_FC2 + (size_t)l * EMBED * FFN_DIM,
            fc2_b + l * EMBED, EMBED, FFN_DIM, 0, nullptr, py, nullptr);
        float* lnout = (l == 3) ? (float*)d_out : px;
        ln_kernel<<<NROWS / 8, 256>>>(px, py, ln3_g + l * EMBED, ln3_b + l * EMBED, lnout, pxh);
    }
}

// round 15
// speedup vs baseline: 2.0061x; 1.1204x over previous
#include <cuda_runtime.h>
#include <cuda_fp16.h>
#include <cstdint>

#define T_SEQ 2048
#define BATCH 2
#define EMBED 512
#define NHEADS 8
#define HD 64
#define FFN_DIM 2048
#define NROWS (T_SEQ * BATCH)      // 4096
#define BH (BATCH * NHEADS)        // 16
#define QKV_LD (3 * EMBED)         // 1536
#define ROWSTRIDE (BATCH * QKV_LD) // 3072
#define S32 40
#define SQ 72

// weight-plane segment offsets (elems) -- hi plane only
#define S_SQKV 0
#define S_SWO  3145728
#define S_CQKV 4194304
#define S_CWO  7340032
#define S_FC1  8388608
#define S_FC2  12582912
#define W_TOT  16777216

// fused-attn smem: Q-hi [0,18432); 2 stages of (K-hi + V-hi) (36864 each)
#define FA_QB 18432
#define FA_VOFF 18432
#define FA_SSTG 36864
#define FA_SMEM (FA_QB + 2 * FA_SSTG)  // 92160

// ---------------- device scratch (pure fp16 activations + fp32 residual) ----------------
__device__ __align__(16) float g_x[NROWS * EMBED];
__device__ __align__(16) float g_y[NROWS * EMBED];
__device__ __align__(16) __half g_xh[NROWS * EMBED];
__device__ __align__(16) __half g_ench[NROWS * EMBED];
__device__ __align__(16) __half g_qkvh[NROWS * QKV_LD];
__device__ __align__(16) __half g_hidh[NROWS * FFN_DIM];
__device__ __align__(16) __half g_ah[NROWS * EMBED];
__device__ __align__(16) __half g_wbh[W_TOT];
__device__ float g_vsum[BATCH * EMBED];
__device__ float g_vs2[BATCH * EMBED];
__device__ unsigned g_minmax[2];

__device__ __forceinline__ unsigned fenc(float f) {
    unsigned u = __float_as_uint(f);
    return (u & 0x80000000u) ? ~u : (u | 0x80000000u);
}
__device__ __forceinline__ float fdec(unsigned e) {
    return __uint_as_float((e & 0x80000000u) ? (e ^ 0x80000000u) : ~e);
}
__device__ __forceinline__ uint32_t smem_u32(const void* p) {
    uint32_t a;
    asm("{ .reg .u64 t; cvta.to.shared.u64 t, %1; cvt.u32.u64 %0, t; }" : "=r"(a) : "l"(p));
    return a;
}
__device__ __forceinline__ void cpa16(uint32_t d, const void* s) {
    asm volatile("cp.async.cg.shared.global [%0], [%1], 16;" :: "r"(d), "l"(s));
}
#define CPA_COMMIT() asm volatile("cp.async.commit_group;" ::: "memory")
#define CPA_WAIT0()  asm volatile("cp.async.wait_group 0;" ::: "memory")
#define CPA_WAIT1()  asm volatile("cp.async.wait_group 1;" ::: "memory")

__device__ __forceinline__ void ldmx4(uint32_t* r, uint32_t addr) {
    asm volatile("ldmatrix.sync.aligned.m8n8.x4.shared.b16 {%0,%1,%2,%3}, [%4];"
        : "=r"(r[0]), "=r"(r[1]), "=r"(r[2]), "=r"(r[3]) : "r"(addr));
}
__device__ __forceinline__ void ldmx4t(uint32_t* r, uint32_t addr) {
    asm volatile("ldmatrix.sync.aligned.m8n8.x4.trans.shared.b16 {%0,%1,%2,%3}, [%4];"
        : "=r"(r[0]), "=r"(r[1]), "=r"(r[2]), "=r"(r[3]) : "r"(addr));
}
__device__ __forceinline__ void mma16816(float* c, const uint32_t* a, const uint32_t* b) {
    asm volatile("mma.sync.aligned.m16n8k16.row.col.f32.f16.f16.f32 "
        "{%0,%1,%2,%3}, {%4,%5,%6,%7}, {%8,%9}, {%0,%1,%2,%3};"
        : "+f"(c[0]), "+f"(c[1]), "+f"(c[2]), "+f"(c[3])
        : "r"(a[0]), "r"(a[1]), "r"(a[2]), "r"(a[3]), "r"(b[0]), "r"(b[1]));
}
__device__ __forceinline__ uint2 pack4h(float4 v) {
    __half2 h01 = __floats2half2_rn(v.x, v.y);
    __half2 h23 = __floats2half2_rn(v.z, v.w);
    uint2 u;
    u.x = *(uint32_t*)&h01; u.y = *(uint32_t*)&h23;
    return u;
}
__device__ __forceinline__ uint32_t pack2h(float v0, float v1) {
    __half2 hh = __floats2half2_rn(v0, v1);
    return *(uint32_t*)&hh;
}

// ---------------- small kernels ----------------
__global__ void cvt_hi(const float* __restrict__ src, __half* __restrict__ dh, int n4) {
    int i = blockIdx.x * 256 + threadIdx.x;
    if (i >= n4) return;
    ((uint2*)dh)[i] = pack4h(((const float4*)src)[i]);
}

__global__ void posembed_kernel(const float* __restrict__ x,
                                const int* __restrict__ tokens) {
    int i = blockIdx.x * 256 + threadIdx.x;
    int c4 = (i & 127) * 4;
    int row = i >> 7;
    int t = row >> 1, b = row & 1;
    int tok = tokens[b * T_SEQ + t];
    float4 v = ((const float4*)x)[i];
    if (tok != 0) {
        float p = (float)(t + 1);
        float* pv = (float*)&v;
#pragma unroll
        for (int e = 0; e < 4; e++) {
            int c = c4 + e;
            int ii = (c < 256) ? c : c - 256;
            float ang = p * expf((float)ii * (-9.210340371976184f / 255.0f));
            pv[e] += (c < 256) ? sinf(ang) : cosf(ang);
        }
    }
    ((float4*)g_x)[i] = v;
    ((uint2*)g_xh)[i] = pack4h(v);
}

// vsum over V-hi (matches the V actually used by AV) + folded min/max init
__global__ void vsum_kernel(int selfmask) {
    const int bh = blockIdx.x;
    if (bh == 0 && threadIdx.x == 0) {
        if (selfmask) { g_minmax[0] = fenc(0.f); g_minmax[1] = fenc(0.f); }
        else          { g_minmax[0] = 0xFFFFFFFFu; g_minmax[1] = 0u; }
    }
    const int b = bh >> 3, h = bh & 7;
    const __half* vh = g_qkvh + b * QKV_LD + 2 * EMBED + h * HD;
    const int d = threadIdx.x & 63;
    const int part = threadIdx.x >> 6;
    float s = 0.f;
    for (int i = part * 512; i < part * 512 + 512; i++)
        s += __half2float(vh[(size_t)i * ROWSTRIDE + d]);
    __shared__ float sm[256];
    sm[threadIdx.x] = s;
    __syncthreads();
    if (threadIdx.x < 64)
        g_vsum[b * EMBED + h * HD + d] = sm[d] + sm[64 + d] + sm[128 + d] + sm[192 + d];
}

// vs2[b][n] = sum_c vsum[b][c] * Wo_hi[n][c]  (consistent with the fp16 proj GEMM)
__global__ void vs2_kernel(const __half* __restrict__ Wo) {
    int idx = blockIdx.x * 256 + threadIdx.x;  // 1024
    int b = idx >> 9, n = idx & 511;
    const float* vs = g_vsum + b * EMBED;
    const __half2* w2 = (const __half2*)(Wo + (size_t)n * EMBED);
    float s = 0.f;
    for (int c2 = 0; c2 < 256; c2++) {
        float2 f = __half22float2(w2[c2]);
        s += vs[2 * c2] * f.x + vs[2 * c2 + 1] * f.y;
    }
    g_vs2[idx] = s;
}

// warp-per-row LN (fp32 residual out + fp16 hi plane)
__global__ __launch_bounds__(256)
void ln_kernel(const float* __restrict__ res, const float* __restrict__ y,
               const float* __restrict__ gam, const float* __restrict__ bet,
               float* __restrict__ out, __half* __restrict__ outh) {
    const int row = blockIdx.x * 8 + (threadIdx.x >> 5);
    const int lane = threadIdx.x & 31;
    const size_t base = (size_t)row * EMBED;
    float v[16];
    float s = 0.f, q = 0.f;
#pragma unroll
    for (int k = 0; k < 4; k++) {
        const int c = lane * 4 + k * 128;
        float4 a = *(const float4*)(res + base + c);
        float4 bb = *(const float4*)(y + base + c);
        float t0 = a.x + bb.x, t1 = a.y + bb.y, t2 = a.z + bb.z, t3 = a.w + bb.w;
        v[k * 4 + 0] = t0; v[k * 4 + 1] = t1; v[k * 4 + 2] = t2; v[k * 4 + 3] = t3;
        s += t0 + t1 + t2 + t3;
        q += t0 * t0 + t1 * t1 + t2 * t2 + t3 * t3;
    }
#pragma unroll
    for (int off = 16; off > 0; off >>= 1) {
        s += __shfl_xor_sync(0xffffffffu, s, off);
        q += __shfl_xor_sync(0xffffffffu, q, off);
    }
    const float mu = s * (1.f / 512.f);
    const float var = q * (1.f / 512.f) - mu * mu;
    const float rs = rsqrtf(fmaxf(var, 0.f) + 1e-20f);
#pragma unroll
    for (int k = 0; k < 4; k++) {
        const int c = lane * 4 + k * 128;
        float4 g4 = *(const float4*)(gam + c);
        float4 b4 = *(const float4*)(bet + c);
        float4 o;
        o.x = (v[k * 4 + 0] - mu) * rs * g4.x + b4.x;
        o.y = (v[k * 4 + 1] - mu) * rs * g4.y + b4.y;
        o.z = (v[k * 4 + 2] - mu) * rs * g4.z + b4.z;
        o.w = (v[k * 4 + 3] - mu) * rs * g4.w + b4.w;
        *(float4*)(out + base + c) = o;
        *(uint2*)(outh + base + c) = pack4h(o);
    }
}

// ---------------- fused attention: single-plane fp16 (R14-verified) ----------------
__global__ __launch_bounds__(256, 1)
void fused_attn(int selfmask) {
    const int bid = blockIdx.x;
    const int bh = bid & 15, b = bh >> 3, h = bh & 7;
    const int tile = bid >> 4;
    const int bt = (selfmask ? (15 - tile) : tile) * 128;
    extern __shared__ char dyn[];
    const uint32_t u0 = smem_u32(dyn);
    const int tid = threadIdx.x, wid = tid >> 5, lane = tid & 31;
    const int trow = wid * 16;
    const __half* qh = g_qkvh + b * QKV_LD + h * HD;
    const __half* kh = g_qkvh + b * QKV_LD + EMBED + h * HD;
    const __half* vh = g_qkvh + b * QKV_LD + 2 * EMBED + h * HD;
    const int nst = selfmask ? (bt / 128 + 1) : 16;

#pragma unroll 1
    for (int i = tid; i < 1024; i += 256) {
        int r = i >> 3, c = (i & 7) * 8;
        cpa16(u0 + (r * SQ + c) * 2, qh + (size_t)(bt + r) * ROWSTRIDE + c);
        uint32_t dk = u0 + FA_QB + (r * SQ + c) * 2;
        cpa16(dk,           kh + (size_t)r * ROWSTRIDE + c);
        cpa16(dk + FA_VOFF, vh + (size_t)r * ROWSTRIDE + c);
    }
    CPA_COMMIT();

    uint32_t qfh[4][4];
    float oacc[8][4] = {};
    float lmin = 3.4e38f, lmax = -3.4e38f;

    for (int st = 0; st < nst; st++) {
        const uint32_t sb = u0 + FA_QB + (st & 1) * FA_SSTG;
        if (st + 1 < nst) {
            const uint32_t nb = u0 + FA_QB + ((st + 1) & 1) * FA_SSTG;
            const int s0 = (st + 1) * 128;
#pragma unroll 1
            for (int i = tid; i < 1024; i += 256) {
                int r = i >> 3, c = (i & 7) * 8;
                uint32_t dk = nb + (r * SQ + c) * 2;
                cpa16(dk,           kh + (size_t)(s0 + r) * ROWSTRIDE + c);
                cpa16(dk + FA_VOFF, vh + (size_t)(s0 + r) * ROWSTRIDE + c);
            }
            CPA_COMMIT();
            CPA_WAIT1();
        } else {
            CPA_WAIT0();
        }
        __syncthreads();
        if (st == 0) {
#pragma unroll
            for (int ks = 0; ks < 4; ks++) {
                uint32_t off = u0 + ((trow + (lane & 15)) * SQ + ks * 16 + (lane >> 4) * 8) * 2;
                ldmx4(qfh[ks], off);
            }
        }
        // ---- S = Q @ K^T ----
        float sacc[16][4] = {};
#pragma unroll
        for (int ks = 0; ks < 4; ks++) {
#pragma unroll
            for (int j4 = 0; j4 < 8; j4++) {
                uint32_t off = sb + ((j4 * 16 + ((lane >> 4) & 1) * 8 + (lane & 7)) * SQ
                               + ks * 16 + ((lane >> 3) & 1) * 8) * 2;
                uint32_t kbh[4];
                ldmx4(kbh, off);
#pragma unroll
                for (int jj = 0; jj < 2; jj++)
                    mma16816(sacc[j4 * 2 + jj], qfh[ks], &kbh[jj * 2]);
            }
        }
        // ---- scale/mask/minmax + register repack C-frag -> A-frag ----
        const int diag = selfmask && (st == nst - 1);
        const int tg0 = bt + trow + (lane >> 2);
        const int sg0 = st * 128 + (lane & 3) * 2;
        uint32_t sfh[8][4];
#pragma unroll
        for (int j = 0; j < 16; j++) {
            float v0 = sacc[j][0] * 0.125f, v1 = sacc[j][1] * 0.125f;
            float v2 = sacc[j][2] * 0.125f, v3 = sacc[j][3] * 0.125f;
            if (diag) {
                int s = sg0 + j * 8;
                if (s + 0 > tg0) v0 = 0.f;
                if (s + 1 > tg0) v1 = 0.f;
                if (s + 0 > tg0 + 8) v2 = 0.f;
                if (s + 1 > tg0 + 8) v3 = 0.f;
            }
            lmin = fminf(lmin, fminf(fminf(v0, v1), fminf(v2, v3)));
            lmax = fmaxf(lmax, fmaxf(fmaxf(v0, v1), fmaxf(v2, v3)));
            int p = j >> 1, q = (j & 1) * 2;
            sfh[p][q] = pack2h(v0, v1);
            sfh[p][q + 1] = pack2h(v2, v3);
        }
        // ---- O += S @ V ----
        const uint32_t vb = sb + FA_VOFF;
#pragma unroll
        for (int p = 0; p < 8; p++) {
#pragma unroll
            for (int jd4 = 0; jd4 < 4; jd4++) {
                uint32_t off = vb + ((p * 16 + (lane & 15)) * SQ + jd4 * 16 + (lane >> 4) * 8) * 2;
                uint32_t vbh[4];
                ldmx4t(vbh, off);
#pragma unroll
                for (int jj = 0; jj < 2; jj++)
                    mma16816(oacc[jd4 * 2 + jj], sfh[p], &vbh[jj * 2]);
            }
        }
        __syncthreads();
    }

    // ---- epilogue: write O_raw hi plane ----
    const int r = lane >> 2, tig = lane & 3;
#pragma unroll
    for (int jd = 0; jd < 8; jd++) {
        const int d = jd * 8 + tig * 2;
#pragma unroll
        for (int half = 0; half < 2; half++) {
            const int t = bt + trow + r + half * 8;
            size_t off = (size_t)(t * BATCH + b) * EMBED + h * HD + d;
            *(uint32_t*)(g_ah + off) = pack2h(oacc[jd][half * 2], oacc[jd][half * 2 + 1]);
        }
    }
#pragma unroll
    for (int off = 16; off > 0; off >>= 1) {
        lmin = fminf(lmin, __shfl_xor_sync(0xffffffffu, lmin, off));
        lmax = fmaxf(lmax, __shfl_xor_sync(0xffffffffu, lmax, off));
    }
    __shared__ float rmn[8], rmx[8];
    if (lane == 0) { rmn[wid] = lmin; rmx[wid] = lmax; }
    __syncthreads();
    if (tid == 0) {
        float mn = rmn[0], mx = rmx[0];
#pragma unroll
        for (int w = 1; w < 8; w++) { mn = fminf(mn, rmn[w]); mx = fmaxf(mx, rmx[w]); }
        atomicMin(&g_minmax[0], fenc(mn));
        atomicMax(&g_minmax[1], fenc(mx));
    }
}

// ---------------- mma linear: pure fp16, NOW 2 CTAs/SM ----------------
// mode 0: fp32 out; 1: fp16 hi out; 2: hi + relu; 3: fp32 + deferred minmax norm
#define LIN_STG 20480
__global__ __launch_bounds__(256, 2)
void mma_linear(const __half* __restrict__ Aqh, const __half* __restrict__ Akvh,
                int nsplit,
                const __half* __restrict__ Bh,
                const float* __restrict__ bias, int N, int K, int mode,
                const float* __restrict__ vs2,
                float* __restrict__ Cf, __half* __restrict__ Ch) {
    extern __shared__ char dyn[];
    const uint32_t u0 = smem_u32(dyn);
    const int tid = threadIdx.x, wid = tid >> 5, lane = tid & 31;
    const int bn = blockIdx.x * 128, bm = blockIdx.y * 128;
    const __half* Ah = (bn < nsplit) ? Aqh : Akvh;
    const int wm = (wid >> 2) * 64, wn = (wid & 3) * 32;

    float acc[4][4][4] = {};
    const int nkt = K >> 5;

#pragma unroll 1
    for (int i = tid; i < 512; i += 256) {
        int r = i >> 2, c = (i & 3) * 8;
        uint32_t d = u0 + (r * S32 + c) * 2;
        cpa16(d,         Ah + (size_t)(bm + r) * K + c);
        cpa16(d + 10240, Bh + (size_t)(bn + r) * K + c);
    }
    CPA_COMMIT();

    for (int kt = 0; kt < nkt; kt++) {
        const uint32_t sb = u0 + (kt & 1) * LIN_STG;
        if (kt + 1 < nkt) {
            const uint32_t nb = u0 + ((kt + 1) & 1) * LIN_STG;
            const int kc = (kt + 1) * 32;
#pragma unroll 1
            for (int i = tid; i < 512; i += 256) {
                int r = i >> 2, c = (i & 3) * 8;
                uint32_t d = nb + (r * S32 + c) * 2;
                cpa16(d,         Ah + (size_t)(bm + r) * K + kc + c);
                cpa16(d + 10240, Bh + (size_t)(bn + r) * K + kc + c);
            }
            CPA_COMMIT();
            CPA_WAIT1();
        } else {
            CPA_WAIT0();
        }
        __syncthreads();
#pragma unroll
        for (int ks = 0; ks < 2; ks++) {
            uint32_t ah[4][4], bh[2][4];
#pragma unroll
            for (int i = 0; i < 4; i++) {
                uint32_t off = sb + ((wm + i * 16 + (lane & 15)) * S32 + ks * 16 + (lane >> 4) * 8) * 2;
                ldmx4(ah[i], off);
            }
#pragma unroll
            for (int j2 = 0; j2 < 2; j2++) {
                uint32_t off = sb + ((wn + j2 * 16 + ((lane >> 4) & 1) * 8 + (lane & 7)) * S32
                               + ks * 16 + ((lane >> 3) & 1) * 8) * 2;
                ldmx4(bh[j2], off + 10240);
            }
#pragma unroll
            for (int i = 0; i < 4; i++)
#pragma unroll
                for (int j = 0; j < 4; j++)
                    mma16816(acc[i][j], ah[i], &bh[j >> 1][(j & 1) * 2]);
        }
        __syncthreads();
    }
    float mn = 0.f, inv = 1.f;
    if (mode == 3) {
        mn = fdec(g_minmax[0]);
        inv = 1.f / (fdec(g_minmax[1]) - mn);
    }
#pragma unroll
    for (int i = 0; i < 4; i++) {
        const int m0 = bm + wm + i * 16 + (lane >> 2);
#pragma unroll
        for (int j = 0; j < 4; j++) {
            const int n0 = bn + wn + j * 8 + (lane & 3) * 2;
            float b0 = bias[n0], b1 = bias[n0 + 1];
#pragma unroll
            for (int half = 0; half < 2; half++) {
                const int m = m0 + half * 8;
                float v0 = acc[i][j][half * 2 + 0];
                float v1 = acc[i][j][half * 2 + 1];
                if (mode == 3) {
                    const int bb = m & 1;
                    v0 = (v0 - mn * vs2[bb * EMBED + n0]) * inv + b0;
                    v1 = (v1 - mn * vs2[bb * EMBED + n0 + 1]) * inv + b1;
                    *(float2*)(Cf + (size_t)m * N + n0) = make_float2(v0, v1);
                } else {
                    v0 += b0; v1 += b1;
                    if (mode == 2) { v0 = fmaxf(v0, 0.f); v1 = fmaxf(v1, 0.f); }
                    if (mode == 0) {
                        *(float2*)(Cf + (size_t)m * N + n0) = make_float2(v0, v1);
                    } else {
                        *(uint32_t*)(Ch + (size_t)m * N + n0) = pack2h(v0, v1);
                    }
                }
            }
        }
    }
}

// ---------------- host orchestration ----------------
extern "C" void kernel_launch(void* const* d_in, const int* in_sizes, int n_in,
                              void* d_out, int out_size) {
    const float* x         = (const float*)d_in[0];
    const float* enc_out   = (const float*)d_in[1];
    const int*   tokens    = (const int*)d_in[2];
    const float* self_Wqkv = (const float*)d_in[3];
    const float* self_bqkv = (const float*)d_in[4];
    const float* self_Wo   = (const float*)d_in[5];
    const float* self_bo   = (const float*)d_in[6];
    const float* cross_Wqkv= (const float*)d_in[7];
    const float* cross_bqkv= (const float*)d_in[8];
    const float* cross_Wo  = (const float*)d_in[9];
    const float* cross_bo  = (const float*)d_in[10];
    const float* fc1_w     = (const float*)d_in[11];
    const float* fc1_b     = (const float*)d_in[12];
    const float* fc2_w     = (const float*)d_in[13];
    const float* fc2_b     = (const float*)d_in[14];
    const float* ln1_g     = (const float*)d_in[15];
    const float* ln1_b     = (const float*)d_in[16];
    const float* ln2_g     = (const float*)d_in[17];
    const float* ln2_b     = (const float*)d_in[18];
    const float* ln3_g     = (const float*)d_in[19];
    const float* ln3_b     = (const float*)d_in[20];

    float *px, *py, *pvs2;
    __half *pxh, *pench, *pqkvh, *phidh, *pah, *pwbh;
    cudaGetSymbolAddress((void**)&px, g_x);
    cudaGetSymbolAddress((void**)&py, g_y);
    cudaGetSymbolAddress((void**)&pvs2, g_vs2);
    cudaGetSymbolAddress((void**)&pxh, g_xh);
    cudaGetSymbolAddress((void**)&pench, g_ench);
    cudaGetSymbolAddress((void**)&pqkvh, g_qkvh);
    cudaGetSymbolAddress((void**)&phidh, g_hidh);
    cudaGetSymbolAddress((void**)&pah, g_ah);
    cudaGetSymbolAddress((void**)&pwbh, g_wbh);

    const int SM_LIN = 2 * LIN_STG;  // 40960
    cudaFuncSetAttribute(mma_linear, cudaFuncAttributeMaxDynamicSharedMemorySize, SM_LIN);
    cudaFuncSetAttribute(fused_attn, cudaFuncAttributeMaxDynamicSharedMemorySize, FA_SMEM);

    auto cvtw = [&](const float* src, size_t off, int n) {
        cvt_hi<<<(n / 4 + 255) / 256, 256>>>(src, pwbh + off, n / 4);
    };
    cvtw(self_Wqkv, S_SQKV, 4 * QKV_LD * EMBED);
    cvtw(self_Wo,   S_SWO,  4 * EMBED * EMBED);
    cvtw(cross_Wqkv,S_CQKV, 4 * QKV_LD * EMBED);
    cvtw(cross_Wo,  S_CWO,  4 * EMBED * EMBED);
    cvtw(fc1_w,     S_FC1,  4 * FFN_DIM * EMBED);
    cvtw(fc2_w,     S_FC2,  4 * EMBED * FFN_DIM);
    cvt_hi<<<(NROWS * EMBED / 4 + 255) / 256, 256>>>(enc_out, pench, NROWS * EMBED / 4);

    posembed_kernel<<<NROWS * EMBED / 4 / 256, 256>>>(x, tokens);

    const int BIG = 1 << 30;
    for (int l = 0; l < 4; l++) {
        // ---- self attention ----
        mma_linear<<<dim3(12, 32), 256, SM_LIN>>>(pxh, pxh, BIG,
            pwbh + S_SQKV + (size_t)l * QKV_LD * EMBED,
            self_bqkv + l * QKV_LD, QKV_LD, EMBED, 1, nullptr, nullptr, pqkvh);
        vsum_kernel<<<16, 256>>>(1);
        fused_attn<<<256, 256, FA_SMEM>>>(1);
        vs2_kernel<<<4, 256>>>(pwbh + S_SWO + (size_t)l * EMBED * EMBED);
        mma_linear<<<dim3(4, 32), 256, SM_LIN>>>(pah, pah, BIG,
            pwbh + S_SWO + (size_t)l * EMBED * EMBED,
            self_bo + l * EMBED, EMBED, EMBED, 3, pvs2, py, nullptr);
        ln_kernel<<<NROWS / 8, 256>>>(px, py, ln1_g + l * EMBED, ln1_b + l * EMBED, px, pxh);

        // ---- cross attention ----
        mma_linear<<<dim3(12, 32), 256, SM_LIN>>>(pxh, pench, EMBED,
            pwbh + S_CQKV + (size_t)l * QKV_LD * EMBED,
            cross_bqkv + l * QKV_LD, QKV_LD, EMBED, 1, nullptr, nullptr, pqkvh);
        vsum_kernel<<<16, 256>>>(0);
        fused_attn<<<256, 256, FA_SMEM>>>(0);
        vs2_kernel<<<4, 256>>>(pwbh + S_CWO + (size_t)l * EMBED * EMBED);
        mma_linear<<<dim3(4, 32), 256, SM_LIN>>>(pah, pah, BIG,
            pwbh + S_CWO + (size_t)l * EMBED * EMBED,
            cross_bo + l * EMBED, EMBED, EMBED, 3, pvs2, py, nullptr);
        ln_kernel<<<NROWS / 8, 256>>>(px, py, ln2_g + l * EMBED, ln2_b + l * EMBED, px, pxh);

        // ---- FFN ----
        mma_linear<<<dim3(16, 32), 256, SM_LIN>>>(pxh, pxh, BIG,
            pwbh + S_FC1 + (size_t)l * FFN_DIM * EMBED,
            fc1_b + l * FFN_DIM, FFN_DIM, EMBED, 2, nullptr, nullptr, phidh);
        mma_linear<<<dim3(4, 32), 256, SM_LIN>>>(phidh, phidh, BIG,
            pwbh + S_FC2 + (size_t)l * EMBED * FFN_DIM,
            fc2_b + l * EMBED, EMBED, FFN_DIM, 0, nullptr, py, nullptr);
        float* lnout = (l == 3) ? (float*)d_out : px;
        ln_kernel<<<NROWS / 8, 256>>>(px, py, ln3_g + l * EMBED, ln3_b + l * EMBED, lnout, pxh);
    }
}

// round 16
// speedup vs baseline: 2.0218x; 1.0079x over previous
#include <cuda_runtime.h>
#include <cuda_fp16.h>
#include <cstdint>

#define T_SEQ 2048
#define BATCH 2
#define EMBED 512
#define NHEADS 8
#define HD 64
#define FFN_DIM 2048
#define NROWS (T_SEQ * BATCH)      // 4096
#define BH (BATCH * NHEADS)        // 16
#define QKV_LD (3 * EMBED)         // 1536
#define ROWSTRIDE (BATCH * QKV_LD) // 3072
#define S32 40
#define SQ 72

// weight-plane segment offsets (elems) -- hi plane only
#define S_SQKV 0
#define S_SWO  3145728
#define S_CQKV 4194304
#define S_CWO  7340032
#define S_FC1  8388608
#define S_FC2  12582912
#define W_TOT  16777216

// fused-attn smem: Q-hi [0,18432); 2 stages of (K-hi + V-hi) (36864 each)
#define FA_QB 18432
#define FA_VOFF 18432
#define FA_SSTG 36864
#define FA_SMEM (FA_QB + 2 * FA_SSTG)  // 92160; 2 CTAs/SM = 180KB, fits

// ---------------- device scratch (pure fp16 activations + fp32 residual) ----------------
__device__ __align__(16) float g_x[NROWS * EMBED];
__device__ __align__(16) float g_y[NROWS * EMBED];
__device__ __align__(16) __half g_xh[NROWS * EMBED];
__device__ __align__(16) __half g_ench[NROWS * EMBED];
__device__ __align__(16) __half g_qkvh[NROWS * QKV_LD];
__device__ __align__(16) __half g_hidh[NROWS * FFN_DIM];
__device__ __align__(16) __half g_ah[NROWS * EMBED];
__device__ __align__(16) __half g_wbh[W_TOT];
__device__ float g_vsum[BATCH * EMBED];
__device__ float g_vs2[BATCH * EMBED];
__device__ unsigned g_minmax[2];

__device__ __forceinline__ unsigned fenc(float f) {
    unsigned u = __float_as_uint(f);
    return (u & 0x80000000u) ? ~u : (u | 0x80000000u);
}
__device__ __forceinline__ float fdec(unsigned e) {
    return __uint_as_float((e & 0x80000000u) ? (e ^ 0x80000000u) : ~e);
}
__device__ __forceinline__ uint32_t smem_u32(const void* p) {
    uint32_t a;
    asm("{ .reg .u64 t; cvta.to.shared.u64 t, %1; cvt.u32.u64 %0, t; }" : "=r"(a) : "l"(p));
    return a;
}
__device__ __forceinline__ void cpa16(uint32_t d, const void* s) {
    asm volatile("cp.async.cg.shared.global [%0], [%1], 16;" :: "r"(d), "l"(s));
}
#define CPA_COMMIT() asm volatile("cp.async.commit_group;" ::: "memory")
#define CPA_WAIT0()  asm volatile("cp.async.wait_group 0;" ::: "memory")
#define CPA_WAIT1()  asm volatile("cp.async.wait_group 1;" ::: "memory")

__device__ __forceinline__ void ldmx4(uint32_t* r, uint32_t addr) {
    asm volatile("ldmatrix.sync.aligned.m8n8.x4.shared.b16 {%0,%1,%2,%3}, [%4];"
        : "=r"(r[0]), "=r"(r[1]), "=r"(r[2]), "=r"(r[3]) : "r"(addr));
}
__device__ __forceinline__ void ldmx4t(uint32_t* r, uint32_t addr) {
    asm volatile("ldmatrix.sync.aligned.m8n8.x4.trans.shared.b16 {%0,%1,%2,%3}, [%4];"
        : "=r"(r[0]), "=r"(r[1]), "=r"(r[2]), "=r"(r[3]) : "r"(addr));
}
__device__ __forceinline__ void mma16816(float* c, const uint32_t* a, const uint32_t* b) {
    asm volatile("mma.sync.aligned.m16n8k16.row.col.f32.f16.f16.f32 "
        "{%0,%1,%2,%3}, {%4,%5,%6,%7}, {%8,%9}, {%0,%1,%2,%3};"
        : "+f"(c[0]), "+f"(c[1]), "+f"(c[2]), "+f"(c[3])
        : "r"(a[0]), "r"(a[1]), "r"(a[2]), "r"(a[3]), "r"(b[0]), "r"(b[1]));
}
__device__ __forceinline__ uint2 pack4h(float4 v) {
    __half2 h01 = __floats2half2_rn(v.x, v.y);
    __half2 h23 = __floats2half2_rn(v.z, v.w);
    uint2 u;
    u.x = *(uint32_t*)&h01; u.y = *(uint32_t*)&h23;
    return u;
}
__device__ __forceinline__ uint32_t pack2h(float v0, float v1) {
    __half2 hh = __floats2half2_rn(v0, v1);
    return *(uint32_t*)&hh;
}

// ---------------- small kernels ----------------
__global__ void cvt_hi(const float* __restrict__ src, __half* __restrict__ dh, int n4) {
    int i = blockIdx.x * 256 + threadIdx.x;
    if (i >= n4) return;
    ((uint2*)dh)[i] = pack4h(((const float4*)src)[i]);
}

__global__ void posembed_kernel(const float* __restrict__ x,
                                const int* __restrict__ tokens) {
    int i = blockIdx.x * 256 + threadIdx.x;
    int c4 = (i & 127) * 4;
    int row = i >> 7;
    int t = row >> 1, b = row & 1;
    int tok = tokens[b * T_SEQ + t];
    float4 v = ((const float4*)x)[i];
    if (tok != 0) {
        float p = (float)(t + 1);
        float* pv = (float*)&v;
#pragma unroll
        for (int e = 0; e < 4; e++) {
            int c = c4 + e;
            int ii = (c < 256) ? c : c - 256;
            float ang = p * expf((float)ii * (-9.210340371976184f / 255.0f));
            pv[e] += (c < 256) ? sinf(ang) : cosf(ang);
        }
    }
    ((float4*)g_x)[i] = v;
    ((uint2*)g_xh)[i] = pack4h(v);
}

// vsum over V-hi + folded min/max init
__global__ void vsum_kernel(int selfmask) {
    const int bh = blockIdx.x;
    if (bh == 0 && threadIdx.x == 0) {
        if (selfmask) { g_minmax[0] = fenc(0.f); g_minmax[1] = fenc(0.f); }
        else          { g_minmax[0] = 0xFFFFFFFFu; g_minmax[1] = 0u; }
    }
    const int b = bh >> 3, h = bh & 7;
    const __half* vh = g_qkvh + b * QKV_LD + 2 * EMBED + h * HD;
    const int d = threadIdx.x & 63;
    const int part = threadIdx.x >> 6;
    float s = 0.f;
    for (int i = part * 512; i < part * 512 + 512; i++)
        s += __half2float(vh[(size_t)i * ROWSTRIDE + d]);
    __shared__ float sm[256];
    sm[threadIdx.x] = s;
    __syncthreads();
    if (threadIdx.x < 64)
        g_vsum[b * EMBED + h * HD + d] = sm[d] + sm[64 + d] + sm[128 + d] + sm[192 + d];
}

// vs2[b][n] = sum_c vsum[b][c] * Wo_hi[n][c]
__global__ void vs2_kernel(const __half* __restrict__ Wo) {
    int idx = blockIdx.x * 256 + threadIdx.x;  // 1024
    int b = idx >> 9, n = idx & 511;
    const float* vs = g_vsum + b * EMBED;
    const __half2* w2 = (const __half2*)(Wo + (size_t)n * EMBED);
    float s = 0.f;
    for (int c2 = 0; c2 < 256; c2++) {
        float2 f = __half22float2(w2[c2]);
        s += vs[2 * c2] * f.x + vs[2 * c2 + 1] * f.y;
    }
    g_vs2[idx] = s;
}

// warp-per-row LN (fp32 residual out + fp16 hi plane)
__global__ __launch_bounds__(256)
void ln_kernel(const float* __restrict__ res, const float* __restrict__ y,
               const float* __restrict__ gam, const float* __restrict__ bet,
               float* __restrict__ out, __half* __restrict__ outh) {
    const int row = blockIdx.x * 8 + (threadIdx.x >> 5);
    const int lane = threadIdx.x & 31;
    const size_t base = (size_t)row * EMBED;
    float v[16];
    float s = 0.f, q = 0.f;
#pragma unroll
    for (int k = 0; k < 4; k++) {
        const int c = lane * 4 + k * 128;
        float4 a = *(const float4*)(res + base + c);
        float4 bb = *(const float4*)(y + base + c);
        float t0 = a.x + bb.x, t1 = a.y + bb.y, t2 = a.z + bb.z, t3 = a.w + bb.w;
        v[k * 4 + 0] = t0; v[k * 4 + 1] = t1; v[k * 4 + 2] = t2; v[k * 4 + 3] = t3;
        s += t0 + t1 + t2 + t3;
        q += t0 * t0 + t1 * t1 + t2 * t2 + t3 * t3;
    }
#pragma unroll
    for (int off = 16; off > 0; off >>= 1) {
        s += __shfl_xor_sync(0xffffffffu, s, off);
        q += __shfl_xor_sync(0xffffffffu, q, off);
    }
    const float mu = s * (1.f / 512.f);
    const float var = q * (1.f / 512.f) - mu * mu;
    const float rs = rsqrtf(fmaxf(var, 0.f) + 1e-20f);
#pragma unroll
    for (int k = 0; k < 4; k++) {
        const int c = lane * 4 + k * 128;
        float4 g4 = *(const float4*)(gam + c);
        float4 b4 = *(const float4*)(bet + c);
        float4 o;
        o.x = (v[k * 4 + 0] - mu) * rs * g4.x + b4.x;
        o.y = (v[k * 4 + 1] - mu) * rs * g4.y + b4.y;
        o.z = (v[k * 4 + 2] - mu) * rs * g4.z + b4.z;
        o.w = (v[k * 4 + 3] - mu) * rs * g4.w + b4.w;
        *(float4*)(out + base + c) = o;
        *(uint2*)(outh + base + c) = pack4h(o);
    }
}

// ---------------- fused attention: single-plane fp16, NOW 2 CTAs/SM ----------------
__global__ __launch_bounds__(256, 2)
void fused_attn(int selfmask) {
    const int bid = blockIdx.x;
    const int bh = bid & 15, b = bh >> 3, h = bh & 7;
    const int tile = bid >> 4;
    const int bt = (selfmask ? (15 - tile) : tile) * 128;
    extern __shared__ char dyn[];
    const uint32_t u0 = smem_u32(dyn);
    const int tid = threadIdx.x, wid = tid >> 5, lane = tid & 31;
    const int trow = wid * 16;
    const __half* qh = g_qkvh + b * QKV_LD + h * HD;
    const __half* kh = g_qkvh + b * QKV_LD + EMBED + h * HD;
    const __half* vh = g_qkvh + b * QKV_LD + 2 * EMBED + h * HD;
    const int nst = selfmask ? (bt / 128 + 1) : 16;

#pragma unroll 1
    for (int i = tid; i < 1024; i += 256) {
        int r = i >> 3, c = (i & 7) * 8;
        cpa16(u0 + (r * SQ + c) * 2, qh + (size_t)(bt + r) * ROWSTRIDE + c);
        uint32_t dk = u0 + FA_QB + (r * SQ + c) * 2;
        cpa16(dk,           kh + (size_t)r * ROWSTRIDE + c);
        cpa16(dk + FA_VOFF, vh + (size_t)r * ROWSTRIDE + c);
    }
    CPA_COMMIT();

    uint32_t qfh[4][4];
    float oacc[8][4] = {};
    float lmin = 3.4e38f, lmax = -3.4e38f;

    for (int st = 0; st < nst; st++) {
        const uint32_t sb = u0 + FA_QB + (st & 1) * FA_SSTG;
        if (st + 1 < nst) {
            const uint32_t nb = u0 + FA_QB + ((st + 1) & 1) * FA_SSTG;
            const int s0 = (st + 1) * 128;
#pragma unroll 1
            for (int i = tid; i < 1024; i += 256) {
                int r = i >> 3, c = (i & 7) * 8;
                uint32_t dk = nb + (r * SQ + c) * 2;
                cpa16(dk,           kh + (size_t)(s0 + r) * ROWSTRIDE + c);
                cpa16(dk + FA_VOFF, vh + (size_t)(s0 + r) * ROWSTRIDE + c);
            }
            CPA_COMMIT();
            CPA_WAIT1();
        } else {
            CPA_WAIT0();
        }
        __syncthreads();
        if (st == 0) {
#pragma unroll
            for (int ks = 0; ks < 4; ks++) {
                uint32_t off = u0 + ((trow + (lane & 15)) * SQ + ks * 16 + (lane >> 4) * 8) * 2;
                ldmx4(qfh[ks], off);
            }
        }
        // ---- S = Q @ K^T ----
        float sacc[16][4] = {};
#pragma unroll
        for (int ks = 0; ks < 4; ks++) {
#pragma unroll
            for (int j4 = 0; j4 < 8; j4++) {
                uint32_t off = sb + ((j4 * 16 + ((lane >> 4) & 1) * 8 + (lane & 7)) * SQ
                               + ks * 16 + ((lane >> 3) & 1) * 8) * 2;
                uint32_t kbh[4];
                ldmx4(kbh, off);
#pragma unroll
                for (int jj = 0; jj < 2; jj++)
                    mma16816(sacc[j4 * 2 + jj], qfh[ks], &kbh[jj * 2]);
            }
        }
        // ---- scale/mask/minmax + register repack C-frag -> A-frag ----
        const int diag = selfmask && (st == nst - 1);
        const int tg0 = bt + trow + (lane >> 2);
        const int sg0 = st * 128 + (lane & 3) * 2;
        uint32_t sfh[8][4];
#pragma unroll
        for (int j = 0; j < 16; j++) {
            float v0 = sacc[j][0] * 0.125f, v1 = sacc[j][1] * 0.125f;
            float v2 = sacc[j][2] * 0.125f, v3 = sacc[j][3] * 0.125f;
            if (diag) {
                int s = sg0 + j * 8;
                if (s + 0 > tg0) v0 = 0.f;
                if (s + 1 > tg0) v1 = 0.f;
                if (s + 0 > tg0 + 8) v2 = 0.f;
                if (s + 1 > tg0 + 8) v3 = 0.f;
            }
            lmin = fminf(lmin, fminf(fminf(v0, v1), fminf(v2, v3)));
            lmax = fmaxf(lmax, fmaxf(fmaxf(v0, v1), fmaxf(v2, v3)));
            int p = j >> 1, q = (j & 1) * 2;
            sfh[p][q] = pack2h(v0, v1);
            sfh[p][q + 1] = pack2h(v2, v3);
        }
        // ---- O += S @ V ----
        const uint32_t vb = sb + FA_VOFF;
#pragma unroll
        for (int p = 0; p < 8; p++) {
#pragma unroll
            for (int jd4 = 0; jd4 < 4; jd4++) {
                uint32_t off = vb + ((p * 16 + (lane & 15)) * SQ + jd4 * 16 + (lane >> 4) * 8) * 2;
                uint32_t vbh[4];
                ldmx4t(vbh, off);
#pragma unroll
                for (int jj = 0; jj < 2; jj++)
                    mma16816(oacc[jd4 * 2 + jj], sfh[p], &vbh[jj * 2]);
            }
        }
        __syncthreads();
    }

    // ---- epilogue: write O_raw hi plane ----
    const int r = lane >> 2, tig = lane & 3;
#pragma unroll
    for (int jd = 0; jd < 8; jd++) {
        const int d = jd * 8 + tig * 2;
#pragma unroll
        for (int half = 0; half < 2; half++) {
            const int t = bt + trow + r + half * 8;
            size_t off = (size_t)(t * BATCH + b) * EMBED + h * HD + d;
            *(uint32_t*)(g_ah + off) = pack2h(oacc[jd][half * 2], oacc[jd][half * 2 + 1]);
        }
    }
#pragma unroll
    for (int off = 16; off > 0; off >>= 1) {
        lmin = fminf(lmin, __shfl_xor_sync(0xffffffffu, lmin, off));
        lmax = fmaxf(lmax, __shfl_xor_sync(0xffffffffu, lmax, off));
    }
    __shared__ float rmn[8], rmx[8];
    if (lane == 0) { rmn[wid] = lmin; rmx[wid] = lmax; }
    __syncthreads();
    if (tid == 0) {
        float mn = rmn[0], mx = rmx[0];
#pragma unroll
        for (int w = 1; w < 8; w++) { mn = fminf(mn, rmn[w]); mx = fmaxf(mx, rmx[w]); }
        atomicMin(&g_minmax[0], fenc(mn));
        atomicMax(&g_minmax[1], fenc(mx));
    }
}

// ---------------- mma linear: pure fp16, 2 CTAs/SM ----------------
// mode 0: fp32 out; 1: fp16 hi out; 2: hi + relu; 3: fp32 + deferred minmax norm
#define LIN_STG 20480
__global__ __launch_bounds__(256, 2)
void mma_linear(const __half* __restrict__ Aqh, const __half* __restrict__ Akvh,
                int nsplit,
                const __half* __restrict__ Bh,
                const float* __restrict__ bias, int N, int K, int mode,
                const float* __restrict__ vs2,
                float* __restrict__ Cf, __half* __restrict__ Ch) {
    extern __shared__ char dyn[];
    const uint32_t u0 = smem_u32(dyn);
    const int tid = threadIdx.x, wid = tid >> 5, lane = tid & 31;
    const int bn = blockIdx.x * 128, bm = blockIdx.y * 128;
    const __half* Ah = (bn < nsplit) ? Aqh : Akvh;
    const int wm = (wid >> 2) * 64, wn = (wid & 3) * 32;

    float acc[4][4][4] = {};
    const int nkt = K >> 5;

#pragma unroll 1
    for (int i = tid; i < 512; i += 256) {
        int r = i >> 2, c = (i & 3) * 8;
        uint32_t d = u0 + (r * S32 + c) * 2;
        cpa16(d,         Ah + (size_t)(bm + r) * K + c);
        cpa16(d + 10240, Bh + (size_t)(bn + r) * K + c);
    }
    CPA_COMMIT();

    for (int kt = 0; kt < nkt; kt++) {
        const uint32_t sb = u0 + (kt & 1) * LIN_STG;
        if (kt + 1 < nkt) {
            const uint32_t nb = u0 + ((kt + 1) & 1) * LIN_STG;
            const int kc = (kt + 1) * 32;
#pragma unroll 1
            for (int i = tid; i < 512; i += 256) {
                int r = i >> 2, c = (i & 3) * 8;
                uint32_t d = nb + (r * S32 + c) * 2;
                cpa16(d,         Ah + (size_t)(bm + r) * K + kc + c);
                cpa16(d + 10240, Bh + (size_t)(bn + r) * K + kc + c);
            }
            CPA_COMMIT();
            CPA_WAIT1();
        } else {
            CPA_WAIT0();
        }
        __syncthreads();
#pragma unroll
        for (int ks = 0; ks < 2; ks++) {
            uint32_t ah[4][4], bh[2][4];
#pragma unroll
            for (int i = 0; i < 4; i++) {
                uint32_t off = sb + ((wm + i * 16 + (lane & 15)) * S32 + ks * 16 + (lane >> 4) * 8) * 2;
                ldmx4(ah[i], off);
            }
#pragma unroll
            for (int j2 = 0; j2 < 2; j2++) {
                uint32_t off = sb + ((wn + j2 * 16 + ((lane >> 4) & 1) * 8 + (lane & 7)) * S32
                               + ks * 16 + ((lane >> 3) & 1) * 8) * 2;
                ldmx4(bh[j2], off + 10240);
            }
#pragma unroll
            for (int i = 0; i < 4; i++)
#pragma unroll
                for (int j = 0; j < 4; j++)
                    mma16816(acc[i][j], ah[i], &bh[j >> 1][(j & 1) * 2]);
        }
        __syncthreads();
    }
    float mn = 0.f, inv = 1.f;
    if (mode == 3) {
        mn = fdec(g_minmax[0]);
        inv = 1.f / (fdec(g_minmax[1]) - mn);
    }
#pragma unroll
    for (int i = 0; i < 4; i++) {
        const int m0 = bm + wm + i * 16 + (lane >> 2);
#pragma unroll
        for (int j = 0; j < 4; j++) {
            const int n0 = bn + wn + j * 8 + (lane & 3) * 2;
            float b0 = bias[n0], b1 = bias[n0 + 1];
#pragma unroll
            for (int half = 0; half < 2; half++) {
                const int m = m0 + half * 8;
                float v0 = acc[i][j][half * 2 + 0];
                float v1 = acc[i][j][half * 2 + 1];
                if (mode == 3) {
                    const int bb = m & 1;
                    v0 = (v0 - mn * vs2[bb * EMBED + n0]) * inv + b0;
                    v1 = (v1 - mn * vs2[bb * EMBED + n0 + 1]) * inv + b1;
                    *(float2*)(Cf + (size_t)m * N + n0) = make_float2(v0, v1);
                } else {
                    v0 += b0; v1 += b1;
                    if (mode == 2) { v0 = fmaxf(v0, 0.f); v1 = fmaxf(v1, 0.f); }
                    if (mode == 0) {
                        *(float2*)(Cf + (size_t)m * N + n0) = make_float2(v0, v1);
                    } else {
                        *(uint32_t*)(Ch + (size_t)m * N + n0) = pack2h(v0, v1);
                    }
                }
            }
        }
    }
}

// ---------------- host orchestration ----------------
extern "C" void kernel_launch(void* const* d_in, const int* in_sizes, int n_in,
                              void* d_out, int out_size) {
    const float* x         = (const float*)d_in[0];
    const float* enc_out   = (const float*)d_in[1];
    const int*   tokens    = (const int*)d_in[2];
    const float* self_Wqkv = (const float*)d_in[3];
    const float* self_bqkv = (const float*)d_in[4];
    const float* self_Wo   = (const float*)d_in[5];
    const float* self_bo   = (const float*)d_in[6];
    const float* cross_Wqkv= (const float*)d_in[7];
    const float* cross_bqkv= (const float*)d_in[8];
    const float* cross_Wo  = (const float*)d_in[9];
    const float* cross_bo  = (const float*)d_in[10];
    const float* fc1_w     = (const float*)d_in[11];
    const float* fc1_b     = (const float*)d_in[12];
    const float* fc2_w     = (const float*)d_in[13];
    const float* fc2_b     = (const float*)d_in[14];
    const float* ln1_g     = (const float*)d_in[15];
    const float* ln1_b     = (const float*)d_in[16];
    const float* ln2_g     = (const float*)d_in[17];
    const float* ln2_b     = (const float*)d_in[18];
    const float* ln3_g     = (const float*)d_in[19];
    const float* ln3_b     = (const float*)d_in[20];

    float *px, *py, *pvs2;
    __half *pxh, *pench, *pqkvh, *phidh, *pah, *pwbh;
    cudaGetSymbolAddress((void**)&px, g_x);
    cudaGetSymbolAddress((void**)&py, g_y);
    cudaGetSymbolAddress((void**)&pvs2, g_vs2);
    cudaGetSymbolAddress((void**)&pxh, g_xh);
    cudaGetSymbolAddress((void**)&pench, g_ench);
    cudaGetSymbolAddress((void**)&pqkvh, g_qkvh);
    cudaGetSymbolAddress((void**)&phidh, g_hidh);
    cudaGetSymbolAddress((void**)&pah, g_ah);
    cudaGetSymbolAddress((void**)&pwbh, g_wbh);

    const int SM_LIN = 2 * LIN_STG;  // 40960
    cudaFuncSetAttribute(mma_linear, cudaFuncAttributeMaxDynamicSharedMemorySize, SM_LIN);
    cudaFuncSetAttribute(fused_attn, cudaFuncAttributeMaxDynamicSharedMemorySize, FA_SMEM);

    auto cvtw = [&](const float* src, size_t off, int n) {
        cvt_hi<<<(n / 4 + 255) / 256, 256>>>(src, pwbh + off, n / 4);
    };
    cvtw(self_Wqkv, S_SQKV, 4 * QKV_LD * EMBED);
    cvtw(self_Wo,   S_SWO,  4 * EMBED * EMBED);
    cvtw(cross_Wqkv,S_CQKV, 4 * QKV_LD * EMBED);
    cvtw(cross_Wo,  S_CWO,  4 * EMBED * EMBED);
    cvtw(fc1_w,     S_FC1,  4 * FFN_DIM * EMBED);
    cvtw(fc2_w,     S_FC2,  4 * EMBED * FFN_DIM);
    cvt_hi<<<(NROWS * EMBED / 4 + 255) / 256, 256>>>(enc_out, pench, NROWS * EMBED / 4);

    posembed_kernel<<<NROWS * EMBED / 4 / 256, 256>>>(x, tokens);

    const int BIG = 1 << 30;
    for (int l = 0; l < 4; l++) {
        // ---- self attention ----
        mma_linear<<<dim3(12, 32), 256, SM_LIN>>>(pxh, pxh, BIG,
            pwbh + S_SQKV + (size_t)l * QKV_LD * EMBED,
            self_bqkv + l * QKV_LD, QKV_LD, EMBED, 1, nullptr, nullptr, pqkvh);
        vsum_kernel<<<16, 256>>>(1);
        fused_attn<<<256, 256, FA_SMEM>>>(1);
        vs2_kernel<<<4, 256>>>(pwbh + S_SWO + (size_t)l * EMBED * EMBED);
        mma_linear<<<dim3(4, 32), 256, SM_LIN>>>(pah, pah, BIG,
            pwbh + S_SWO + (size_t)l * EMBED * EMBED,
            self_bo + l * EMBED, EMBED, EMBED, 3, pvs2, py, nullptr);
        ln_kernel<<<NROWS / 8, 256>>>(px, py, ln1_g + l * EMBED, ln1_b + l * EMBED, px, pxh);

        // ---- cross attention ----
        mma_linear<<<dim3(12, 32), 256, SM_LIN>>>(pxh, pench, EMBED,
            pwbh + S_CQKV + (size_t)l * QKV_LD * EMBED,
            cross_bqkv + l * QKV_LD, QKV_LD, EMBED, 1, nullptr, nullptr, pqkvh);
        vsum_kernel<<<16, 256>>>(0);
        fused_attn<<<256, 256, FA_SMEM>>>(0);
        vs2_kernel<<<4, 256>>>(pwbh + S_CWO + (size_t)l * EMBED * EMBED);
        mma_linear<<<dim3(4, 32), 256, SM_LIN>>>(pah, pah, BIG,
            pwbh + S_CWO + (size_t)l * EMBED * EMBED,
            cross_bo + l * EMBED, EMBED, EMBED, 3, pvs2, py, nullptr);
        ln_kernel<<<NROWS / 8, 256>>>(px, py, ln2_g + l * EMBED, ln2_b + l * EMBED, px, pxh);

        // ---- FFN ----
        mma_linear<<<dim3(16, 32), 256, SM_LIN>>>(pxh, pxh, BIG,
            pwbh + S_FC1 + (size_t)l * FFN_DIM * EMBED,
            fc1_b + l * FFN_DIM, FFN_DIM, EMBED, 2, nullptr, nullptr, phidh);
        mma_linear<<<dim3(4, 32), 256, SM_LIN>>>(phidh, phidh, BIG,
            pwbh + S_FC2 + (size_t)l * EMBED * FFN_DIM,
            fc2_b + l * EMBED, EMBED, FFN_DIM, 0, nullptr, py, nullptr);
        float* lnout = (l == 3) ? (float*)d_out : px;
        ln_kernel<<<NROWS / 8, 256>>>(px, py, ln3_g + l * EMBED, ln3_b + l * EMBED, lnout, pxh);
    }
}

// round 17
// speedup vs baseline: 2.1153x; 1.0462x over previous
#include <cuda_runtime.h>
#include <cuda_fp16.h>
#include <cstdint>

#define T_SEQ 2048
#define BATCH 2
#define EMBED 512
#define NHEADS 8
#define HD 64
#define FFN_DIM 2048
#define NROWS (T_SEQ * BATCH)      // 4096
#define BH (BATCH * NHEADS)        // 16
#define QKV_LD (3 * EMBED)         // 1536
#define ROWSTRIDE (BATCH * QKV_LD) // 3072
#define S32 40
#define SQ 72

// weight-plane segment offsets (elems) -- hi plane only
#define S_SQKV 0
#define S_SWO  3145728
#define S_CQKV 4194304
#define S_CWO  7340032
#define S_FC1  8388608
#define S_FC2  12582912
#define W_TOT  16777216

// fused-attn smem: Q-hi [0,18432); 2 stages of (K-hi + V-hi) (36864 each)
#define FA_QB 18432
#define FA_VOFF 18432
#define FA_SSTG 36864
#define FA_SMEM (FA_QB + 2 * FA_SSTG)  // 92160

// ---------------- device scratch (pure fp16 activations + fp32 residual) ----------------
__device__ __align__(16) float g_x[NROWS * EMBED];
__device__ __align__(16) float g_y[NROWS * EMBED];
__device__ __align__(16) __half g_xh[NROWS * EMBED];
__device__ __align__(16) __half g_ench[NROWS * EMBED];
__device__ __align__(16) __half g_qkvh[NROWS * QKV_LD];
__device__ __align__(16) __half g_hidh[NROWS * FFN_DIM];
__device__ __align__(16) __half g_ah[NROWS * EMBED];
__device__ __align__(16) __half g_wbh[W_TOT];
__device__ float g_vsum[BATCH * EMBED];
__device__ float g_vs2[BATCH * EMBED];
__device__ unsigned g_minmax[2];

__device__ __forceinline__ unsigned fenc(float f) {
    unsigned u = __float_as_uint(f);
    return (u & 0x80000000u) ? ~u : (u | 0x80000000u);
}
__device__ __forceinline__ float fdec(unsigned e) {
    return __uint_as_float((e & 0x80000000u) ? (e ^ 0x80000000u) : ~e);
}
__device__ __forceinline__ uint32_t smem_u32(const void* p) {
    uint32_t a;
    asm("{ .reg .u64 t; cvta.to.shared.u64 t, %1; cvt.u32.u64 %0, t; }" : "=r"(a) : "l"(p));
    return a;
}
__device__ __forceinline__ void cpa16(uint32_t d, const void* s) {
    asm volatile("cp.async.cg.shared.global [%0], [%1], 16;" :: "r"(d), "l"(s));
}
#define CPA_COMMIT() asm volatile("cp.async.commit_group;" ::: "memory")
#define CPA_WAIT0()  asm volatile("cp.async.wait_group 0;" ::: "memory")
#define CPA_WAIT1()  asm volatile("cp.async.wait_group 1;" ::: "memory")

__device__ __forceinline__ void ldmx4(uint32_t* r, uint32_t addr) {
    asm volatile("ldmatrix.sync.aligned.m8n8.x4.shared.b16 {%0,%1,%2,%3}, [%4];"
        : "=r"(r[0]), "=r"(r[1]), "=r"(r[2]), "=r"(r[3]) : "r"(addr));
}
__device__ __forceinline__ void ldmx4t(uint32_t* r, uint32_t addr) {
    asm volatile("ldmatrix.sync.aligned.m8n8.x4.trans.shared.b16 {%0,%1,%2,%3}, [%4];"
        : "=r"(r[0]), "=r"(r[1]), "=r"(r[2]), "=r"(r[3]) : "r"(addr));
}
__device__ __forceinline__ void mma16816(float* c, const uint32_t* a, const uint32_t* b) {
    asm volatile("mma.sync.aligned.m16n8k16.row.col.f32.f16.f16.f32 "
        "{%0,%1,%2,%3}, {%4,%5,%6,%7}, {%8,%9}, {%0,%1,%2,%3};"
        : "+f"(c[0]), "+f"(c[1]), "+f"(c[2]), "+f"(c[3])
        : "r"(a[0]), "r"(a[1]), "r"(a[2]), "r"(a[3]), "r"(b[0]), "r"(b[1]));
}
__device__ __forceinline__ uint2 pack4h(float4 v) {
    __half2 h01 = __floats2half2_rn(v.x, v.y);
    __half2 h23 = __floats2half2_rn(v.z, v.w);
    uint2 u;
    u.x = *(uint32_t*)&h01; u.y = *(uint32_t*)&h23;
    return u;
}
__device__ __forceinline__ uint32_t pack2h(float v0, float v1) {
    __half2 hh = __floats2half2_rn(v0, v1);
    return *(uint32_t*)&hh;
}

// ---------------- small kernels ----------------
__global__ void cvt_hi(const float* __restrict__ src, __half* __restrict__ dh, int n4) {
    int i = blockIdx.x * 256 + threadIdx.x;
    if (i >= n4) return;
    ((uint2*)dh)[i] = pack4h(((const float4*)src)[i]);
}

__global__ void posembed_kernel(const float* __restrict__ x,
                                const int* __restrict__ tokens) {
    int i = blockIdx.x * 256 + threadIdx.x;
    int c4 = (i & 127) * 4;
    int row = i >> 7;
    int t = row >> 1, b = row & 1;
    int tok = tokens[b * T_SEQ + t];
    float4 v = ((const float4*)x)[i];
    if (tok != 0) {
        float p = (float)(t + 1);
        float* pv = (float*)&v;
#pragma unroll
        for (int e = 0; e < 4; e++) {
            int c = c4 + e;
            int ii = (c < 256) ? c : c - 256;
            float ang = p * expf((float)ii * (-9.210340371976184f / 255.0f));
            pv[e] += (c < 256) ? sinf(ang) : cosf(ang);
        }
    }
    ((float4*)g_x)[i] = v;
    ((uint2*)g_xh)[i] = pack4h(v);
}

// vsum over V-hi: 1024-thread blocks (16 partials/d, fixed-order deterministic reduce)
__global__ __launch_bounds__(1024)
void vsum_kernel(int selfmask) {
    const int bh = blockIdx.x;
    if (bh == 0 && threadIdx.x == 0) {
        if (selfmask) { g_minmax[0] = fenc(0.f); g_minmax[1] = fenc(0.f); }
        else          { g_minmax[0] = 0xFFFFFFFFu; g_minmax[1] = 0u; }
    }
    const int b = bh >> 3, h = bh & 7;
    const __half* vh = g_qkvh + b * QKV_LD + 2 * EMBED + h * HD;
    const int d = threadIdx.x & 63;
    const int part = threadIdx.x >> 6;   // [0,16)
    float s = 0.f;
    for (int i = part * 128; i < part * 128 + 128; i++)
        s += __half2float(vh[(size_t)i * ROWSTRIDE + d]);
    __shared__ float sm[1024];
    sm[threadIdx.x] = s;
    __syncthreads();
    if (threadIdx.x < 64) {
        float acc = 0.f;
#pragma unroll
        for (int p = 0; p < 16; p++) acc += sm[p * 64 + d];
        g_vsum[b * EMBED + h * HD + d] = acc;
    }
}

// vs2[b][n] = sum_c vsum[b][c] * Wo_hi[n][c]
__global__ void vs2_kernel(const __half* __restrict__ Wo) {
    int idx = blockIdx.x * 256 + threadIdx.x;  // 1024
    int b = idx >> 9, n = idx & 511;
    const float* vs = g_vsum + b * EMBED;
    const __half2* w2 = (const __half2*)(Wo + (size_t)n * EMBED);
    float s = 0.f;
    for (int c2 = 0; c2 < 256; c2++) {
        float2 f = __half22float2(w2[c2]);
        s += vs[2 * c2] * f.x + vs[2 * c2 + 1] * f.y;
    }
    g_vs2[idx] = s;
}

// warp-per-row LN (fp32 residual out + fp16 hi plane)
__global__ __launch_bounds__(256)
void ln_kernel(const float* __restrict__ res, const float* __restrict__ y,
               const float* __restrict__ gam, const float* __restrict__ bet,
               float* __restrict__ out, __half* __restrict__ outh) {
    const int row = blockIdx.x * 8 + (threadIdx.x >> 5);
    const int lane = threadIdx.x & 31;
    const size_t base = (size_t)row * EMBED;
    float v[16];
    float s = 0.f, q = 0.f;
#pragma unroll
    for (int k = 0; k < 4; k++) {
        const int c = lane * 4 + k * 128;
        float4 a = *(const float4*)(res + base + c);
        float4 bb = *(const float4*)(y + base + c);
        float t0 = a.x + bb.x, t1 = a.y + bb.y, t2 = a.z + bb.z, t3 = a.w + bb.w;
        v[k * 4 + 0] = t0; v[k * 4 + 1] = t1; v[k * 4 + 2] = t2; v[k * 4 + 3] = t3;
        s += t0 + t1 + t2 + t3;
        q += t0 * t0 + t1 * t1 + t2 * t2 + t3 * t3;
    }
#pragma unroll
    for (int off = 16; off > 0; off >>= 1) {
        s += __shfl_xor_sync(0xffffffffu, s, off);
        q += __shfl_xor_sync(0xffffffffu, q, off);
    }
    const float mu = s * (1.f / 512.f);
    const float var = q * (1.f / 512.f) - mu * mu;
    const float rs = rsqrtf(fmaxf(var, 0.f) + 1e-20f);
#pragma unroll
    for (int k = 0; k < 4; k++) {
        const int c = lane * 4 + k * 128;
        float4 g4 = *(const float4*)(gam + c);
        float4 b4 = *(const float4*)(bet + c);
        float4 o;
        o.x = (v[k * 4 + 0] - mu) * rs * g4.x + b4.x;
        o.y = (v[k * 4 + 1] - mu) * rs * g4.y + b4.y;
        o.z = (v[k * 4 + 2] - mu) * rs * g4.z + b4.z;
        o.w = (v[k * 4 + 3] - mu) * rs * g4.w + b4.w;
        *(float4*)(out + base + c) = o;
        *(uint2*)(outh + base + c) = pack4h(o);
    }
}

// ---------------- fused attention: single-plane fp16, 2 CTAs/SM ----------------
__global__ __launch_bounds__(256, 2)
void fused_attn(int selfmask) {
    const int bid = blockIdx.x;
    const int bh = bid & 15, b = bh >> 3, h = bh & 7;
    const int tile = bid >> 4;
    const int bt = (selfmask ? (15 - tile) : tile) * 128;
    extern __shared__ char dyn[];
    const uint32_t u0 = smem_u32(dyn);
    const int tid = threadIdx.x, wid = tid >> 5, lane = tid & 31;
    const int trow = wid * 16;
    const __half* qh = g_qkvh + b * QKV_LD + h * HD;
    const __half* kh = g_qkvh + b * QKV_LD + EMBED + h * HD;
    const __half* vh = g_qkvh + b * QKV_LD + 2 * EMBED + h * HD;
    const int nst = selfmask ? (bt / 128 + 1) : 16;

#pragma unroll 1
    for (int i = tid; i < 1024; i += 256) {
        int r = i >> 3, c = (i & 7) * 8;
        cpa16(u0 + (r * SQ + c) * 2, qh + (size_t)(bt + r) * ROWSTRIDE + c);
        uint32_t dk = u0 + FA_QB + (r * SQ + c) * 2;
        cpa16(dk,           kh + (size_t)r * ROWSTRIDE + c);
        cpa16(dk + FA_VOFF, vh + (size_t)r * ROWSTRIDE + c);
    }
    CPA_COMMIT();

    uint32_t qfh[4][4];
    float oacc[8][4] = {};
    float lmin = 3.4e38f, lmax = -3.4e38f;

    for (int st = 0; st < nst; st++) {
        const uint32_t sb = u0 + FA_QB + (st & 1) * FA_SSTG;
        if (st + 1 < nst) {
            const uint32_t nb = u0 + FA_QB + ((st + 1) & 1) * FA_SSTG;
            const int s0 = (st + 1) * 128;
#pragma unroll 1
            for (int i = tid; i < 1024; i += 256) {
                int r = i >> 3, c = (i & 7) * 8;
                uint32_t dk = nb + (r * SQ + c) * 2;
                cpa16(dk,           kh + (size_t)(s0 + r) * ROWSTRIDE + c);
                cpa16(dk + FA_VOFF, vh + (size_t)(s0 + r) * ROWSTRIDE + c);
            }
            CPA_COMMIT();
            CPA_WAIT1();
        } else {
            CPA_WAIT0();
        }
        __syncthreads();
        if (st == 0) {
#pragma unroll
            for (int ks = 0; ks < 4; ks++) {
                uint32_t off = u0 + ((trow + (lane & 15)) * SQ + ks * 16 + (lane >> 4) * 8) * 2;
                ldmx4(qfh[ks], off);
            }
        }
        // ---- S = Q @ K^T ----
        float sacc[16][4] = {};
#pragma unroll
        for (int ks = 0; ks < 4; ks++) {
#pragma unroll
            for (int j4 = 0; j4 < 8; j4++) {
                uint32_t off = sb + ((j4 * 16 + ((lane >> 4) & 1) * 8 + (lane & 7)) * SQ
                               + ks * 16 + ((lane >> 3) & 1) * 8) * 2;
                uint32_t kbh[4];
                ldmx4(kbh, off);
#pragma unroll
                for (int jj = 0; jj < 2; jj++)
                    mma16816(sacc[j4 * 2 + jj], qfh[ks], &kbh[jj * 2]);
            }
        }
        // ---- scale/mask/minmax + register repack C-frag -> A-frag ----
        const int diag = selfmask && (st == nst - 1);
        const int tg0 = bt + trow + (lane >> 2);
        const int sg0 = st * 128 + (lane & 3) * 2;
        uint32_t sfh[8][4];
#pragma unroll
        for (int j = 0; j < 16; j++) {
            float v0 = sacc[j][0] * 0.125f, v1 = sacc[j][1] * 0.125f;
            float v2 = sacc[j][2] * 0.125f, v3 = sacc[j][3] * 0.125f;
            if (diag) {
                int s = sg0 + j * 8;
                if (s + 0 > tg0) v0 = 0.f;
                if (s + 1 > tg0) v1 = 0.f;
                if (s + 0 > tg0 + 8) v2 = 0.f;
                if (s + 1 > tg0 + 8) v3 = 0.f;
            }
            lmin = fminf(lmin, fminf(fminf(v0, v1), fminf(v2, v3)));
            lmax = fmaxf(lmax, fmaxf(fmaxf(v0, v1), fmaxf(v2, v3)));
            int p = j >> 1, q = (j & 1) * 2;
            sfh[p][q] = pack2h(v0, v1);
            sfh[p][q + 1] = pack2h(v2, v3);
        }
        // ---- O += S @ V ----
        const uint32_t vb = sb + FA_VOFF;
#pragma unroll
        for (int p = 0; p < 8; p++) {
#pragma unroll
            for (int jd4 = 0; jd4 < 4; jd4++) {
                uint32_t off = vb + ((p * 16 + (lane & 15)) * SQ + jd4 * 16 + (lane >> 4) * 8) * 2;
                uint32_t vbh[4];
                ldmx4t(vbh, off);
#pragma unroll
                for (int jj = 0; jj < 2; jj++)
                    mma16816(oacc[jd4 * 2 + jj], sfh[p], &vbh[jj * 2]);
            }
        }
        __syncthreads();
    }

    // ---- epilogue: write O_raw hi plane ----
    const int r = lane >> 2, tig = lane & 3;
#pragma unroll
    for (int jd = 0; jd < 8; jd++) {
        const int d = jd * 8 + tig * 2;
#pragma unroll
        for (int half = 0; half < 2; half++) {
            const int t = bt + trow + r + half * 8;
            size_t off = (size_t)(t * BATCH + b) * EMBED + h * HD + d;
            *(uint32_t*)(g_ah + off) = pack2h(oacc[jd][half * 2], oacc[jd][half * 2 + 1]);
        }
    }
#pragma unroll
    for (int off = 16; off > 0; off >>= 1) {
        lmin = fminf(lmin, __shfl_xor_sync(0xffffffffu, lmin, off));
        lmax = fmaxf(lmax, __shfl_xor_sync(0xffffffffu, lmax, off));
    }
    __shared__ float rmn[8], rmx[8];
    if (lane == 0) { rmn[wid] = lmin; rmx[wid] = lmax; }
    __syncthreads();
    if (tid == 0) {
        float mn = rmn[0], mx = rmx[0];
#pragma unroll
        for (int w = 1; w < 8; w++) { mn = fminf(mn, rmn[w]); mx = fmaxf(mx, rmx[w]); }
        atomicMin(&g_minmax[0], fenc(mn));
        atomicMax(&g_minmax[1], fenc(mx));
    }
}

// ---------------- mma linear: pure fp16, 2 CTAs/SM ----------------
// mode 0: fp32 out; 1: fp16 hi out; 2: hi + relu; 3: fp32 + deferred minmax norm
#define LIN_STG 20480
__global__ __launch_bounds__(256, 2)
void mma_linear(const __half* __restrict__ Aqh, const __half* __restrict__ Akvh,
                int nsplit,
                const __half* __restrict__ Bh,
                const float* __restrict__ bias, int N, int K, int mode,
                const float* __restrict__ vs2,
                float* __restrict__ Cf, __half* __restrict__ Ch) {
    extern __shared__ char dyn[];
    const uint32_t u0 = smem_u32(dyn);
    const int tid = threadIdx.x, wid = tid >> 5, lane = tid & 31;
    const int bn = blockIdx.x * 128, bm = blockIdx.y * 128;
    const __half* Ah = (bn < nsplit) ? Aqh : Akvh;
    const int wm = (wid >> 2) * 64, wn = (wid & 3) * 32;

    float acc[4][4][4] = {};
    const int nkt = K >> 5;

#pragma unroll 1
    for (int i = tid; i < 512; i += 256) {
        int r = i >> 2, c = (i & 3) * 8;
        uint32_t d = u0 + (r * S32 + c) * 2;
        cpa16(d,         Ah + (size_t)(bm + r) * K + c);
        cpa16(d + 10240, Bh + (size_t)(bn + r) * K + c);
    }
    CPA_COMMIT();

    for (int kt = 0; kt < nkt; kt++) {
        const uint32_t sb = u0 + (kt & 1) * LIN_STG;
        if (kt + 1 < nkt) {
            const uint32_t nb = u0 + ((kt + 1) & 1) * LIN_STG;
            const int kc = (kt + 1) * 32;
#pragma unroll 1
            for (int i = tid; i < 512; i += 256) {
                int r = i >> 2, c = (i & 3) * 8;
                uint32_t d = nb + (r * S32 + c) * 2;
                cpa16(d,         Ah + (size_t)(bm + r) * K + kc + c);
                cpa16(d + 10240, Bh + (size_t)(bn + r) * K + kc + c);
            }
            CPA_COMMIT();
            CPA_WAIT1();
        } else {
            CPA_WAIT0();
        }
        __syncthreads();
#pragma unroll
        for (int ks = 0; ks < 2; ks++) {
            uint32_t ah[4][4], bh[2][4];
#pragma unroll
            for (int i = 0; i < 4; i++) {
                uint32_t off = sb + ((wm + i * 16 + (lane & 15)) * S32 + ks * 16 + (lane >> 4) * 8) * 2;
                ldmx4(ah[i], off);
            }
#pragma unroll
            for (int j2 = 0; j2 < 2; j2++) {
                uint32_t off = sb + ((wn + j2 * 16 + ((lane >> 4) & 1) * 8 + (lane & 7)) * S32
                               + ks * 16 + ((lane >> 3) & 1) * 8) * 2;
                ldmx4(bh[j2], off + 10240);
            }
#pragma unroll
            for (int i = 0; i < 4; i++)
#pragma unroll
                for (int j = 0; j < 4; j++)
                    mma16816(acc[i][j], ah[i], &bh[j >> 1][(j & 1) * 2]);
        }
        __syncthreads();
    }
    float mn = 0.f, inv = 1.f;
    if (mode == 3) {
        mn = fdec(g_minmax[0]);
        inv = 1.f / (fdec(g_minmax[1]) - mn);
    }
#pragma unroll
    for (int i = 0; i < 4; i++) {
        const int m0 = bm + wm + i * 16 + (lane >> 2);
#pragma unroll
        for (int j = 0; j < 4; j++) {
            const int n0 = bn + wn + j * 8 + (lane & 3) * 2;
            float b0 = bias[n0], b1 = bias[n0 + 1];
#pragma unroll
            for (int half = 0; half < 2; half++) {
                const int m = m0 + half * 8;
                float v0 = acc[i][j][half * 2 + 0];
                float v1 = acc[i][j][half * 2 + 1];
                if (mode == 3) {
                    const int bb = m & 1;
                    v0 = (v0 - mn * vs2[bb * EMBED + n0]) * inv + b0;
                    v1 = (v1 - mn * vs2[bb * EMBED + n0 + 1]) * inv + b1;
                    *(float2*)(Cf + (size_t)m * N + n0) = make_float2(v0, v1);
                } else {
                    v0 += b0; v1 += b1;
                    if (mode == 2) { v0 = fmaxf(v0, 0.f); v1 = fmaxf(v1, 0.f); }
                    if (mode == 0) {
                        *(float2*)(Cf + (size_t)m * N + n0) = make_float2(v0, v1);
                    } else {
                        *(uint32_t*)(Ch + (size_t)m * N + n0) = pack2h(v0, v1);
                    }
                }
            }
        }
    }
}

// ---------------- host orchestration ----------------
extern "C" void kernel_launch(void* const* d_in, const int* in_sizes, int n_in,
                              void* d_out, int out_size) {
    const float* x         = (const float*)d_in[0];
    const float* enc_out   = (const float*)d_in[1];
    const int*   tokens    = (const int*)d_in[2];
    const float* self_Wqkv = (const float*)d_in[3];
    const float* self_bqkv = (const float*)d_in[4];
    const float* self_Wo   = (const float*)d_in[5];
    const float* self_bo   = (const float*)d_in[6];
    const float* cross_Wqkv= (const float*)d_in[7];
    const float* cross_bqkv= (const float*)d_in[8];
    const float* cross_Wo  = (const float*)d_in[9];
    const float* cross_bo  = (const float*)d_in[10];
    const float* fc1_w     = (const float*)d_in[11];
    const float* fc1_b     = (const float*)d_in[12];
    const float* fc2_w     = (const float*)d_in[13];
    const float* fc2_b     = (const float*)d_in[14];
    const float* ln1_g     = (const float*)d_in[15];
    const float* ln1_b     = (const float*)d_in[16];
    const float* ln2_g     = (const float*)d_in[17];
    const float* ln2_b     = (const float*)d_in[18];
    const float* ln3_g     = (const float*)d_in[19];
    const float* ln3_b     = (const float*)d_in[20];

    float *px, *py, *pvs2;
    __half *pxh, *pench, *pqkvh, *phidh, *pah, *pwbh;
    cudaGetSymbolAddress((void**)&px, g_x);
    cudaGetSymbolAddress((void**)&py, g_y);
    cudaGetSymbolAddress((void**)&pvs2, g_vs2);
    cudaGetSymbolAddress((void**)&pxh, g_xh);
    cudaGetSymbolAddress((void**)&pench, g_ench);
    cudaGetSymbolAddress((void**)&pqkvh, g_qkvh);
    cudaGetSymbolAddress((void**)&phidh, g_hidh);
    cudaGetSymbolAddress((void**)&pah, g_ah);
    cudaGetSymbolAddress((void**)&pwbh, g_wbh);

    const int SM_LIN = 2 * LIN_STG;  // 40960
    cudaFuncSetAttribute(mma_linear, cudaFuncAttributeMaxDynamicSharedMemorySize, SM_LIN);
    cudaFuncSetAttribute(fused_attn, cudaFuncAttributeMaxDynamicSharedMemorySize, FA_SMEM);

    auto cvtw = [&](const float* src, size_t off, int n) {
        cvt_hi<<<(n / 4 + 255) / 256, 256>>>(src, pwbh + off, n / 4);
    };
    cvtw(self_Wqkv, S_SQKV, 4 * QKV_LD * EMBED);
    cvtw(self_Wo,   S_SWO,  4 * EMBED * EMBED);
    cvtw(cross_Wqkv,S_CQKV, 4 * QKV_LD * EMBED);
    cvtw(cross_Wo,  S_CWO,  4 * EMBED * EMBED);
    cvtw(fc1_w,     S_FC1,  4 * FFN_DIM * EMBED);
    cvtw(fc2_w,     S_FC2,  4 * EMBED * FFN_DIM);
    cvt_hi<<<(NROWS * EMBED / 4 + 255) / 256, 256>>>(enc_out, pench, NROWS * EMBED / 4);

    posembed_kernel<<<NROWS * EMBED / 4 / 256, 256>>>(x, tokens);

    const int BIG = 1 << 30;
    for (int l = 0; l < 4; l++) {
        // ---- self attention ----
        mma_linear<<<dim3(12, 32), 256, SM_LIN>>>(pxh, pxh, BIG,
            pwbh + S_SQKV + (size_t)l * QKV_LD * EMBED,
            self_bqkv + l * QKV_LD, QKV_LD, EMBED, 1, nullptr, nullptr, pqkvh);
        vsum_kernel<<<16, 1024>>>(1);
        fused_attn<<<256, 256, FA_SMEM>>>(1);
        vs2_kernel<<<4, 256>>>(pwbh + S_SWO + (size_t)l * EMBED * EMBED);
        mma_linear<<<dim3(4, 32), 256, SM_LIN>>>(pah, pah, BIG,
            pwbh + S_SWO + (size_t)l * EMBED * EMBED,
            self_bo + l * EMBED, EMBED, EMBED, 3, pvs2, py, nullptr);
        ln_kernel<<<NROWS / 8, 256>>>(px, py, ln1_g + l * EMBED, ln1_b + l * EMBED, px, pxh);

        // ---- cross attention ----
        mma_linear<<<dim3(12, 32), 256, SM_LIN>>>(pxh, pench, EMBED,
            pwbh + S_CQKV + (size_t)l * QKV_LD * EMBED,
            cross_bqkv + l * QKV_LD, QKV_LD, EMBED, 1, nullptr, nullptr, pqkvh);
        vsum_kernel<<<16, 1024>>>(0);
        fused_attn<<<256, 256, FA_SMEM>>>(0);
        vs2_kernel<<<4, 256>>>(pwbh + S_CWO + (size_t)l * EMBED * EMBED);
        mma_linear<<<dim3(4, 32), 256, SM_LIN>>>(pah, pah, BIG,
            pwbh + S_CWO + (size_t)l * EMBED * EMBED,
            cross_bo + l * EMBED, EMBED, EMBED, 3, pvs2, py, nullptr);
        ln_kernel<<<NROWS / 8, 256>>>(px, py, ln2_g + l * EMBED, ln2_b + l * EMBED, px, pxh);

        // ---- FFN ----
        mma_linear<<<dim3(16, 32), 256, SM_LIN>>>(pxh, pxh, BIG,
            pwbh + S_FC1 + (size_t)l * FFN_DIM * EMBED,
            fc1_b + l * FFN_DIM, FFN_DIM, EMBED, 2, nullptr, nullptr, phidh);
        mma_linear<<<dim3(4, 32), 256, SM_LIN>>>(phidh, phidh, BIG,
            pwbh + S_FC2 + (size_t)l * EMBED * FFN_DIM,
            fc2_b + l * EMBED, EMBED, FFN_DIM, 0, nullptr, py, nullptr);
        float* lnout = (l == 3) ? (float*)d_out : px;
        ln_kernel<<<NROWS / 8, 256>>>(px, py, ln3_g + l * EMBED, ln3_b + l * EMBED, lnout, pxh);
    }
}